// round 5
// baseline (speedup 1.0000x reference)
#include <cuda_runtime.h>
#include <math.h>
#include <stdint.h>

#define N_NODES 50000
#define NP      50048              // padded to 391*128
#define N_EDGES 800000
#define EMBED_DIM 64
#define N_PROPS 3
#define FDIM 192
#define F3 576
#define NCLS2 100
#define STEP_MIN 2
#define STEP_MAX 6

// ---------------- device scratch ----------------
__device__ float g_h [(size_t)NP * FDIM];
__device__ float g_hs[(size_t)NP * FDIM];
__device__ float g_gi[(size_t)NP * F3];
__device__ float g_gh[(size_t)NP * F3];
__device__ float g_wc[(size_t)F3 * FDIM];
__device__ int   g_deg[NP];
__device__ int   g_rowp[NP + 1];
__device__ int   g_cursor[NP];
__device__ int   g_csr[N_EDGES];

// RN-round fp32 -> tf32 bit pattern (low 13 bits zero)
__device__ __forceinline__ float rtf32(float x) {
    uint32_t u = __float_as_uint(x);
    u = (u + 0xfffu + ((u >> 13) & 1u)) & 0xFFFFE000u;
    return __uint_as_float(u);
}

// ================= embedding gather =================
__global__ void embed_gather_kernel(const int* __restrict__ prop_ids,
                                    const float* __restrict__ table) {
    int n = blockIdx.x;
    int f = threadIdx.x;
    int p = f >> 6;
    int e = f & 63;
    int id = prop_ids[n * N_PROPS + p];
    g_h[(size_t)n * FDIM + f] = table[(size_t)id * EMBED_DIM + e];
}

// ================= W_c = W_ih @ W_edge =================
__global__ void fold_kernel(const float* __restrict__ W_ih,
                            const float* __restrict__ W_edge) {
    int i = blockIdx.x;
    int j = threadIdx.x;
    float s = 0.f;
    #pragma unroll 8
    for (int k = 0; k < FDIM; ++k)
        s = fmaf(__ldg(W_ih + i * FDIM + k), __ldg(W_edge + k * FDIM + j), s);
    g_wc[(size_t)i * FDIM + j] = s;
}

// ================= CSR build =================
__global__ void zero_deg_kernel() {
    int i = blockIdx.x * 256 + threadIdx.x;
    if (i < NP) g_deg[i] = 0;
}
__global__ void csr_count_kernel(const int* __restrict__ dst) {
    int e = blockIdx.x * 256 + threadIdx.x;
    if (e < N_EDGES) atomicAdd(&g_deg[dst[e]], 1);
}
__global__ __launch_bounds__(1024) void scan_kernel() {
    __shared__ int part[1024];
    const int CH = 49;
    int t = threadIdx.x;
    int base = t * CH;
    int s = 0;
    #pragma unroll 7
    for (int i = 0; i < CH; ++i) {
        int idx = base + i;
        if (idx < NP) s += g_deg[idx];
    }
    part[t] = s;
    __syncthreads();
    for (int off = 1; off < 1024; off <<= 1) {
        int v = part[t];
        int u = (t >= off) ? part[t - off] : 0;
        __syncthreads();
        part[t] = v + u;
        __syncthreads();
    }
    int run = (t > 0) ? part[t - 1] : 0;
    for (int i = 0; i < CH; ++i) {
        int idx = base + i;
        if (idx < NP) {
            g_rowp[idx]   = run;
            g_cursor[idx] = run;
            run += g_deg[idx];
        }
    }
    if (t == 0) g_rowp[NP] = N_EDGES;
}
__global__ void csr_fill_kernel(const int* __restrict__ src,
                                const int* __restrict__ dst) {
    int e = blockIdx.x * 256 + threadIdx.x;
    if (e < N_EDGES) {
        int p = atomicAdd(&g_cursor[dst[e]], 1);
        g_csr[p] = src[e];
    }
}

// ================= aggregation: hs[n] = sum_{e: dst=n} h[src[e]] =================
__global__ __launch_bounds__(192) void gather_kernel() {
    int g = threadIdx.x / 48;
    int c = threadIdx.x % 48;
    int n = blockIdx.x * 4 + g;
    int beg = __ldg(&g_rowp[n]);
    int end = __ldg(&g_rowp[n + 1]);
    const float4* h4 = reinterpret_cast<const float4*>(g_h);
    float4 v = make_float4(0.f, 0.f, 0.f, 0.f);
    int i = beg;
    for (; i + 2 <= end; i += 2) {
        int s0 = __ldg(&g_csr[i]);
        int s1 = __ldg(&g_csr[i + 1]);
        float4 a = h4[(size_t)s0 * 48 + c];
        float4 b = h4[(size_t)s1 * 48 + c];
        v.x += a.x + b.x; v.y += a.y + b.y;
        v.z += a.z + b.z; v.w += a.w + b.w;
    }
    if (i < end) {
        int s0 = __ldg(&g_csr[i]);
        float4 a = h4[(size_t)s0 * 48 + c];
        v.x += a.x; v.y += a.y; v.z += a.z; v.w += a.w;
    }
    reinterpret_cast<float4*>(g_hs)[(size_t)n * 48 + c] = v;
}

// ================= GRU gate fusion =================
__global__ void gate_kernel() {
    int idx = blockIdx.x * blockDim.x + threadIdx.x;
    if (idx >= N_NODES * 48) return;
    int n = idx / 48;
    int f4 = idx - n * 48;
    const float4* gi = reinterpret_cast<const float4*>(g_gi) + (size_t)n * 144 + f4;
    const float4* gh = reinterpret_cast<const float4*>(g_gh) + (size_t)n * 144 + f4;
    float4 gir = gi[0],  ghr = gh[0];
    float4 giz = gi[48], ghz = gh[48];
    float4 gin = gi[96], ghn = gh[96];
    float4* hp = reinterpret_cast<float4*>(g_h) + (size_t)n * 48 + f4;
    float4 h = *hp, o;
    #define GATE1(X) { \
        float r = 1.f / (1.f + expf(-(gir.X + ghr.X))); \
        float z = 1.f / (1.f + expf(-(giz.X + ghz.X))); \
        float nn = tanhf(gin.X + r * ghn.X); \
        o.X = (1.f - z) * nn + z * h.X; }
    GATE1(x) GATE1(y) GATE1(z) GATE1(w)
    #undef GATE1
    *hp = o;
}

// ================= mma.sync tf32 GEMM (vectorized fragments) =================
// C(M x N) = A(M x 192) @ B(N x 192)^T + bias, optional sigmoid.
// CTA tile 128x64, 8 warps (4x2), warp tile 32x32 (2x4 m16n8k8 atoms).
// BK=32 slab, double-buffered. Smem uses PERMUTED-K layout:
//   phys col k' = (k & 3)*8 + (k >> 2)    (k in [0,32))
// so each thread's 8 fragment values per row are contiguous -> float4 loads.

#define SA 36
#define ASZ (128 * SA)
#define BSZ (64 * SA)
#define SMEM_FLOATS (2 * (ASZ + BSZ))

__device__ __forceinline__ void mma_tf32(float* c, const uint32_t* a, const uint32_t* b) {
    asm volatile(
        "mma.sync.aligned.m16n8k8.row.col.f32.tf32.tf32.f32 "
        "{%0,%1,%2,%3}, {%4,%5,%6,%7}, {%8,%9}, {%0,%1,%2,%3};"
        : "+f"(c[0]), "+f"(c[1]), "+f"(c[2]), "+f"(c[3])
        : "r"(a[0]), "r"(a[1]), "r"(a[2]), "r"(a[3]), "r"(b[0]), "r"(b[1]));
}

__global__ __launch_bounds__(256)
void gemm_mma_kernel(const float* __restrict__ A, const float* __restrict__ B,
                     const float* __restrict__ bias, float* __restrict__ C,
                     int Ntot, int Mstore, int ldc, int act) {
    extern __shared__ float sm[];

    int tid  = threadIdx.x;
    int lane = tid & 31, wid = tid >> 5;
    int wr = wid & 3, wc2 = wid >> 2;
    int lr = lane >> 2, lc = lane & 3;
    int m0 = blockIdx.y * 128;
    int n0 = blockIdx.x * 64;

    float acc[2][4][4];
    #pragma unroll
    for (int i = 0; i < 2; ++i)
        #pragma unroll
        for (int j = 0; j < 4; ++j)
            #pragma unroll
            for (int q = 0; q < 4; ++q) acc[i][j][q] = 0.f;

    float4 ra[4], rb[2];
    int a_row[4], a_c4[4], b_row[2], b_c4[2];
    #pragma unroll
    for (int i = 0; i < 4; ++i) { int it = i * 256 + tid; a_row[i] = it >> 3; a_c4[i] = it & 7; }
    #pragma unroll
    for (int i = 0; i < 2; ++i) { int it = i * 256 + tid; b_row[i] = it >> 3; b_c4[i] = it & 7; }

    #define LOAD_G(k0) { \
        _Pragma("unroll") \
        for (int i = 0; i < 4; ++i) \
            ra[i] = *reinterpret_cast<const float4*>(A + (size_t)(m0 + a_row[i]) * FDIM + (k0) + a_c4[i] * 4); \
        _Pragma("unroll") \
        for (int i = 0; i < 2; ++i) \
            rb[i] = (n0 + b_row[i] < Ntot) \
                ? *reinterpret_cast<const float4*>(B + (size_t)(n0 + b_row[i]) * FDIM + (k0) + b_c4[i] * 4) \
                : make_float4(0.f, 0.f, 0.f, 0.f); \
    }
    // permuted store: global k = c4*4 + j  ->  phys col = j*8 + c4
    #define STORE_S(pbuf) { \
        float* Asp = sm + (pbuf) * (ASZ + BSZ); \
        float* Bsp = Asp + ASZ; \
        _Pragma("unroll") \
        for (int i = 0; i < 4; ++i) { \
            float* p = Asp + a_row[i] * SA + a_c4[i]; \
            p[0]  = rtf32(ra[i].x); p[8]  = rtf32(ra[i].y); \
            p[16] = rtf32(ra[i].z); p[24] = rtf32(ra[i].w); \
        } \
        _Pragma("unroll") \
        for (int i = 0; i < 2; ++i) { \
            float* p = Bsp + b_row[i] * SA + b_c4[i]; \
            p[0]  = rtf32(rb[i].x); p[8]  = rtf32(rb[i].y); \
            p[16] = rtf32(rb[i].z); p[24] = rtf32(rb[i].w); \
        } \
    }

    LOAD_G(0);
    STORE_S(0);
    __syncthreads();

    #pragma unroll 1
    for (int s = 0; s < 6; ++s) {
        if (s < 5) LOAD_G((s + 1) * 32);

        const float* Asp = sm + (s & 1) * (ASZ + BSZ);
        const float* Bsp = Asp + ASZ;

        #pragma unroll
        for (int kp = 0; kp < 2; ++kp) {          // each kp covers ks=2kp, 2kp+1
            int co = lc * 8 + kp * 4;
            float4 fa[4], fb[4];
            #pragma unroll
            for (int q = 0; q < 4; ++q)
                fa[q] = *reinterpret_cast<const float4*>(Asp + (wr * 32 + q * 8 + lr) * SA + co);
            #pragma unroll
            for (int q = 0; q < 4; ++q)
                fb[q] = *reinterpret_cast<const float4*>(Bsp + (wc2 * 32 + q * 8 + lr) * SA + co);

            // sub 0: ks = 2kp (uses .x/.y), sub 1: ks = 2kp+1 (uses .z/.w)
            #pragma unroll
            for (int sub = 0; sub < 2; ++sub) {
                uint32_t a[2][4], b[4][2];
                #pragma unroll
                for (int ma = 0; ma < 2; ++ma) {
                    const float4& f0 = fa[ma * 2];
                    const float4& f1 = fa[ma * 2 + 1];
                    a[ma][0] = __float_as_uint(sub ? f0.z : f0.x);
                    a[ma][1] = __float_as_uint(sub ? f1.z : f1.x);
                    a[ma][2] = __float_as_uint(sub ? f0.w : f0.y);
                    a[ma][3] = __float_as_uint(sub ? f1.w : f1.y);
                }
                #pragma unroll
                for (int na = 0; na < 4; ++na) {
                    b[na][0] = __float_as_uint(sub ? fb[na].z : fb[na].x);
                    b[na][1] = __float_as_uint(sub ? fb[na].w : fb[na].y);
                }
                #pragma unroll
                for (int ma = 0; ma < 2; ++ma)
                    #pragma unroll
                    for (int na = 0; na < 4; ++na)
                        mma_tf32(acc[ma][na], a[ma], b[na]);
            }
        }
        if (s < 5) {
            STORE_S((s + 1) & 1);
            __syncthreads();
        }
    }

    // ---- epilogue ----
    #pragma unroll
    for (int ma = 0; ma < 2; ++ma) {
        #pragma unroll
        for (int na = 0; na < 4; ++na) {
            int row = m0 + wr * 32 + ma * 16 + lr;
            int col = n0 + wc2 * 32 + na * 8 + lc * 2;
            #pragma unroll
            for (int half = 0; half < 2; ++half) {
                int r = row + half * 8;
                if (r >= Mstore) continue;
                float v0 = acc[ma][na][half * 2 + 0];
                float v1 = acc[ma][na][half * 2 + 1];
                if (col + 1 < Ntot) {
                    v0 += __ldg(bias + col);
                    v1 += __ldg(bias + col + 1);
                    if (act) { v0 = 1.f / (1.f + expf(-v0)); v1 = 1.f / (1.f + expf(-v1)); }
                    *reinterpret_cast<float2*>(C + (size_t)r * ldc + col) = make_float2(v0, v1);
                } else if (col < Ntot) {
                    v0 += __ldg(bias + col);
                    if (act) v0 = 1.f / (1.f + expf(-v0));
                    C[(size_t)r * ldc + col] = v0;
                }
            }
        }
    }
}

// ================= launch =================
extern "C" void kernel_launch(void* const* d_in, const int* in_sizes, int n_in,
                              void* d_out, int out_size) {
    const int*   prop_ids = (const int*)d_in[0];
    const int*   src      = (const int*)d_in[1];
    const int*   dst      = (const int*)d_in[2];
    const float* embed    = (const float*)d_in[3];
    const float* W_edge   = (const float*)d_in[4];
    const float* W_ih     = (const float*)d_in[5];
    const float* W_hh     = (const float*)d_in[6];
    const float* b_ih     = (const float*)d_in[7];
    const float* b_hh     = (const float*)d_in[8];
    const float* conv_w   = (const float*)d_in[9];
    const float* conv_b   = (const float*)d_in[10];
    float* out = (float*)d_out;

    float *h, *hs, *gi, *gh, *wc;
    cudaGetSymbolAddress((void**)&h,  g_h);
    cudaGetSymbolAddress((void**)&hs, g_hs);
    cudaGetSymbolAddress((void**)&gi, g_gi);
    cudaGetSymbolAddress((void**)&gh, g_gh);
    cudaGetSymbolAddress((void**)&wc, g_wc);

    static int smem_set = 0;
    if (!smem_set) {
        cudaFuncSetAttribute(gemm_mma_kernel,
                             cudaFuncAttributeMaxDynamicSharedMemorySize,
                             SMEM_FLOATS * 4);
        smem_set = 1;
    }

    const int MT = NP / 128;                       // 391
    const dim3 grid_576(F3 / 64, MT);              // 9 x 391
    const dim3 grid_100((NCLS2 + 63) / 64, MT);    // 2 x 391
    const int gate_grid = (N_NODES * 48 + 255) / 256;
    const int smem_b = SMEM_FLOATS * 4;

    // ---- setup: order chosen so the profiler's captured launch (#4) is the GEMM ----
    embed_gather_kernel<<<N_NODES, FDIM>>>(prop_ids, embed);                    // 1
    fold_kernel<<<F3, FDIM>>>(W_ih, W_edge);                                    // 2
    zero_deg_kernel<<<(NP + 255) / 256, 256>>>();                               // 3
    gemm_mma_kernel<<<grid_576, 256, smem_b>>>(h, W_hh, b_hh, gh, F3, NP, F3, 0); // 4: step-1 gh (independent of CSR)
    csr_count_kernel<<<(N_EDGES + 255) / 256, 256>>>(dst);                      // 5
    scan_kernel<<<1, 1024>>>();                                                 // 6
    csr_fill_kernel<<<(N_EDGES + 255) / 256, 256>>>(src, dst);                  // 7

    // ---- step 1 (gh already computed) ----
    gather_kernel<<<NP / 4, 192>>>();
    gemm_mma_kernel<<<grid_576, 256, smem_b>>>(hs, wc, b_ih, gi, F3, NP, F3, 0);
    gate_kernel<<<gate_grid, 256>>>();

    // ---- steps 2..6 ----
    for (int step = 2; step <= STEP_MAX; ++step) {
        gather_kernel<<<NP / 4, 192>>>();
        gemm_mma_kernel<<<grid_576, 256, smem_b>>>(h,  W_hh, b_hh, gh, F3, NP, F3, 0);
        gemm_mma_kernel<<<grid_576, 256, smem_b>>>(hs, wc,   b_ih, gi, F3, NP, F3, 0);
        gate_kernel<<<gate_grid, 256>>>();
        int s = step - STEP_MIN;
        gemm_mma_kernel<<<grid_100, 256, smem_b>>>(h, conv_w, conv_b, out + s * NCLS2,
                                                   NCLS2, N_NODES, 5 * NCLS2, 1);
    }
}

// round 6
// speedup vs baseline: 1.1404x; 1.1404x over previous
#include <cuda_runtime.h>
#include <math.h>
#include <stdint.h>

#define N_NODES 50000
#define NP      50048              // padded to 391*128
#define N_EDGES 800000
#define EMBED_DIM 64
#define N_PROPS 3
#define FDIM 192
#define F3 576
#define NCLS2 100
#define STEP_MIN 2
#define STEP_MAX 6

// ---------------- device scratch ----------------
__device__ float g_h  [(size_t)NP * FDIM];
__device__ float g_hs [(size_t)NP * FDIM];
__device__ float g_gi [(size_t)NP * F3];
__device__ float g_gh [(size_t)NP * F3];
__device__ float g_wc [(size_t)F3 * FDIM];
__device__ float g_whr[(size_t)F3 * FDIM];
__device__ float g_cwr[(size_t)NCLS2 * FDIM];
__device__ int   g_deg[NP];
__device__ int   g_rowp[NP + 1];
__device__ int   g_cursor[NP];
__device__ int   g_csr[N_EDGES];

// RN-round fp32 -> tf32-representable fp32
__device__ __forceinline__ float rtf32(float x) {
    uint32_t u = __float_as_uint(x);
    u = (u + 0xfffu + ((u >> 13) & 1u)) & 0xFFFFE000u;
    return __uint_as_float(u);
}

// ================= embedding gather (tf32-rounded) =================
__global__ void embed_gather_kernel(const int* __restrict__ prop_ids,
                                    const float* __restrict__ table) {
    int n = blockIdx.x;
    int f = threadIdx.x;
    int p = f >> 6;
    int e = f & 63;
    int id = prop_ids[n * N_PROPS + p];
    g_h[(size_t)n * FDIM + f] = rtf32(table[(size_t)id * EMBED_DIM + e]);
}

// ================= W_c = round(W_ih @ W_edge) =================
__global__ void fold_kernel(const float* __restrict__ W_ih,
                            const float* __restrict__ W_edge) {
    int i = blockIdx.x;
    int j = threadIdx.x;
    float s = 0.f;
    #pragma unroll 8
    for (int k = 0; k < FDIM; ++k)
        s = fmaf(__ldg(W_ih + i * FDIM + k), __ldg(W_edge + k * FDIM + j), s);
    g_wc[(size_t)i * FDIM + j] = rtf32(s);
}

// ================= round W_hh / conv_w into scratch =================
__global__ void round_w_kernel(const float* __restrict__ W_hh,
                               const float* __restrict__ conv_w) {
    int i = blockIdx.x;
    int j = threadIdx.x;
    if (i < F3)
        g_whr[(size_t)i * FDIM + j] = rtf32(__ldg(W_hh + (size_t)i * FDIM + j));
    else
        g_cwr[(size_t)(i - F3) * FDIM + j] = rtf32(__ldg(conv_w + (size_t)(i - F3) * FDIM + j));
}

// ================= CSR build =================
__global__ void zero_deg_kernel() {
    int i = blockIdx.x * 256 + threadIdx.x;
    if (i < NP) g_deg[i] = 0;
}
__global__ void csr_count_kernel(const int* __restrict__ dst) {
    int e = blockIdx.x * 256 + threadIdx.x;
    if (e < N_EDGES) atomicAdd(&g_deg[dst[e]], 1);
}
__global__ __launch_bounds__(1024) void scan_kernel() {
    __shared__ int part[1024];
    const int CH = 49;
    int t = threadIdx.x;
    int base = t * CH;
    int s = 0;
    #pragma unroll 7
    for (int i = 0; i < CH; ++i) {
        int idx = base + i;
        if (idx < NP) s += g_deg[idx];
    }
    part[t] = s;
    __syncthreads();
    for (int off = 1; off < 1024; off <<= 1) {
        int v = part[t];
        int u = (t >= off) ? part[t - off] : 0;
        __syncthreads();
        part[t] = v + u;
        __syncthreads();
    }
    int run = (t > 0) ? part[t - 1] : 0;
    for (int i = 0; i < CH; ++i) {
        int idx = base + i;
        if (idx < NP) {
            g_rowp[idx]   = run;
            g_cursor[idx] = run;
            run += g_deg[idx];
        }
    }
    if (t == 0) g_rowp[NP] = N_EDGES;
}
__global__ void csr_fill_kernel(const int* __restrict__ src,
                                const int* __restrict__ dst) {
    int e = blockIdx.x * 256 + threadIdx.x;
    if (e < N_EDGES) {
        int p = atomicAdd(&g_cursor[dst[e]], 1);
        g_csr[p] = src[e];
    }
}

// ================= aggregation (tf32-rounded output) =================
__global__ __launch_bounds__(192) void gather_kernel() {
    int g = threadIdx.x / 48;
    int c = threadIdx.x % 48;
    int n = blockIdx.x * 4 + g;
    int beg = __ldg(&g_rowp[n]);
    int end = __ldg(&g_rowp[n + 1]);
    const float4* h4 = reinterpret_cast<const float4*>(g_h);
    float4 v = make_float4(0.f, 0.f, 0.f, 0.f);
    int i = beg;
    for (; i + 2 <= end; i += 2) {
        int s0 = __ldg(&g_csr[i]);
        int s1 = __ldg(&g_csr[i + 1]);
        float4 a = h4[(size_t)s0 * 48 + c];
        float4 b = h4[(size_t)s1 * 48 + c];
        v.x += a.x + b.x; v.y += a.y + b.y;
        v.z += a.z + b.z; v.w += a.w + b.w;
    }
    if (i < end) {
        int s0 = __ldg(&g_csr[i]);
        float4 a = h4[(size_t)s0 * 48 + c];
        v.x += a.x; v.y += a.y; v.z += a.z; v.w += a.w;
    }
    v.x = rtf32(v.x); v.y = rtf32(v.y); v.z = rtf32(v.z); v.w = rtf32(v.w);
    reinterpret_cast<float4*>(g_hs)[(size_t)n * 48 + c] = v;
}

// ================= GRU gate fusion (tf32-rounded h) =================
__global__ void gate_kernel() {
    int idx = blockIdx.x * blockDim.x + threadIdx.x;
    if (idx >= N_NODES * 48) return;
    int n = idx / 48;
    int f4 = idx - n * 48;
    const float4* gi = reinterpret_cast<const float4*>(g_gi) + (size_t)n * 144 + f4;
    const float4* gh = reinterpret_cast<const float4*>(g_gh) + (size_t)n * 144 + f4;
    float4 gir = gi[0],  ghr = gh[0];
    float4 giz = gi[48], ghz = gh[48];
    float4 gin = gi[96], ghn = gh[96];
    float4* hp = reinterpret_cast<float4*>(g_h) + (size_t)n * 48 + f4;
    float4 h = *hp, o;
    #define GATE1(X) { \
        float r = 1.f / (1.f + expf(-(gir.X + ghr.X))); \
        float z = 1.f / (1.f + expf(-(giz.X + ghz.X))); \
        float nn = tanhf(gin.X + r * ghn.X); \
        o.X = rtf32((1.f - z) * nn + z * h.X); }
    GATE1(x) GATE1(y) GATE1(z) GATE1(w)
    #undef GATE1
    *hp = o;
}

// ================= mma.sync tf32 GEMM, cp.async 3-stage pipeline =================
// C(M x N) = A(M x 192) @ B(N x 192)^T + bias, optional sigmoid.
// Operands are pre-rounded to tf32 in gmem: no rounding, no staging regs.
// CTA tile 128x64, 8 warps (4x2), warp tile 32x32 (2x4 m16n8k8 atoms).
// BK=32 slab, 3-stage cp.async, SA=36 conflict-free.

#define SA   36
#define AST  (128 * SA)
#define BST  (64 * SA)
#define STG  (AST + BST)
#define SMEM_BYTES (3 * STG * 4)

__device__ __forceinline__ void mma_tf32(float* c, const uint32_t* a, const uint32_t* b) {
    asm volatile(
        "mma.sync.aligned.m16n8k8.row.col.f32.tf32.tf32.f32 "
        "{%0,%1,%2,%3}, {%4,%5,%6,%7}, {%8,%9}, {%0,%1,%2,%3};"
        : "+f"(c[0]), "+f"(c[1]), "+f"(c[2]), "+f"(c[3])
        : "r"(a[0]), "r"(a[1]), "r"(a[2]), "r"(a[3]), "r"(b[0]), "r"(b[1]));
}
__device__ __forceinline__ void cp16(uint32_t saddr, const float* g, int pred) {
    int sz = pred ? 16 : 0;
    asm volatile("cp.async.cg.shared.global [%0], [%1], 16, %2;"
                 :: "r"(saddr), "l"(g), "r"(sz) : "memory");
}

__global__ __launch_bounds__(256)
void gemm_mma_kernel(const float* __restrict__ A, const float* __restrict__ B,
                     const float* __restrict__ bias, float* __restrict__ C,
                     int Ntot, int Mstore, int ldc, int act) {
    extern __shared__ float sm[];
    uint32_t smb;
    asm("{ .reg .u64 t; cvta.to.shared.u64 t, %1; cvt.u32.u64 %0, t; }"
        : "=r"(smb) : "l"(sm));

    int tid  = threadIdx.x;
    int lane = tid & 31, wid = tid >> 5;
    int wr = wid & 3, wc2 = wid >> 2;
    int lr = lane >> 2, lc = lane & 3;
    int m0 = blockIdx.y * 128;
    int n0 = blockIdx.x * 64;

    int a_row[4], a_c4[4], b_row[2], b_c4[2];
    #pragma unroll
    for (int i = 0; i < 4; ++i) { int it = i * 256 + tid; a_row[i] = it >> 3; a_c4[i] = it & 7; }
    #pragma unroll
    for (int i = 0; i < 2; ++i) { int it = i * 256 + tid; b_row[i] = it >> 3; b_c4[i] = it & 7; }

    #define PREFETCH(s, st) { \
        uint32_t sa_ = smb + (st) * (STG * 4); \
        _Pragma("unroll") \
        for (int i = 0; i < 4; ++i) \
            cp16(sa_ + (a_row[i] * SA + a_c4[i] * 4) * 4, \
                 A + (size_t)(m0 + a_row[i]) * FDIM + (s) * 32 + a_c4[i] * 4, 1); \
        uint32_t sb_ = sa_ + AST * 4; \
        _Pragma("unroll") \
        for (int i = 0; i < 2; ++i) \
            cp16(sb_ + (b_row[i] * SA + b_c4[i] * 4) * 4, \
                 B + (size_t)(n0 + b_row[i]) * FDIM + (s) * 32 + b_c4[i] * 4, \
                 (n0 + b_row[i]) < Ntot); \
        asm volatile("cp.async.commit_group;" ::: "memory"); \
    }

    float acc[2][4][4];
    #pragma unroll
    for (int i = 0; i < 2; ++i)
        #pragma unroll
        for (int j = 0; j < 4; ++j)
            #pragma unroll
            for (int q = 0; q < 4; ++q) acc[i][j][q] = 0.f;

    PREFETCH(0, 0);
    PREFETCH(1, 1);

    #pragma unroll 1
    for (int s = 0; s < 6; ++s) {
        asm volatile("cp.async.wait_group 1;" ::: "memory");
        __syncthreads();

        const float* Asp = sm + (s % 3) * STG;
        const float* Bsp = Asp + AST;
        #pragma unroll
        for (int ks = 0; ks < 4; ++ks) {
            int kk = ks * 8 + lc;
            uint32_t a[2][4], b[4][2];
            #pragma unroll
            for (int ma = 0; ma < 2; ++ma) {
                int r = wr * 32 + ma * 16 + lr;
                a[ma][0] = __float_as_uint(Asp[r * SA + kk]);
                a[ma][1] = __float_as_uint(Asp[(r + 8) * SA + kk]);
                a[ma][2] = __float_as_uint(Asp[r * SA + kk + 4]);
                a[ma][3] = __float_as_uint(Asp[(r + 8) * SA + kk + 4]);
            }
            #pragma unroll
            for (int na = 0; na < 4; ++na) {
                int bn = wc2 * 32 + na * 8 + lr;
                b[na][0] = __float_as_uint(Bsp[bn * SA + kk]);
                b[na][1] = __float_as_uint(Bsp[bn * SA + kk + 4]);
            }
            #pragma unroll
            for (int ma = 0; ma < 2; ++ma)
                #pragma unroll
                for (int na = 0; na < 4; ++na)
                    mma_tf32(acc[ma][na], a[ma], b[na]);
        }

        if (s + 2 < 6) {
            PREFETCH(s + 2, (s + 2) % 3);
        } else {
            asm volatile("cp.async.commit_group;" ::: "memory");
        }
    }

    // ---- epilogue ----
    #pragma unroll
    for (int ma = 0; ma < 2; ++ma) {
        #pragma unroll
        for (int na = 0; na < 4; ++na) {
            int row = m0 + wr * 32 + ma * 16 + lr;
            int col = n0 + wc2 * 32 + na * 8 + lc * 2;
            #pragma unroll
            for (int half = 0; half < 2; ++half) {
                int r = row + half * 8;
                if (r >= Mstore) continue;
                float v0 = acc[ma][na][half * 2 + 0];
                float v1 = acc[ma][na][half * 2 + 1];
                if (col + 1 < Ntot) {
                    v0 += __ldg(bias + col);
                    v1 += __ldg(bias + col + 1);
                    if (act) { v0 = 1.f / (1.f + expf(-v0)); v1 = 1.f / (1.f + expf(-v1)); }
                    *reinterpret_cast<float2*>(C + (size_t)r * ldc + col) = make_float2(v0, v1);
                } else if (col < Ntot) {
                    v0 += __ldg(bias + col);
                    if (act) v0 = 1.f / (1.f + expf(-v0));
                    C[(size_t)r * ldc + col] = v0;
                }
            }
        }
    }
}

// ================= launch =================
extern "C" void kernel_launch(void* const* d_in, const int* in_sizes, int n_in,
                              void* d_out, int out_size) {
    const int*   prop_ids = (const int*)d_in[0];
    const int*   src      = (const int*)d_in[1];
    const int*   dst      = (const int*)d_in[2];
    const float* embed    = (const float*)d_in[3];
    const float* W_edge   = (const float*)d_in[4];
    const float* W_ih     = (const float*)d_in[5];
    const float* W_hh     = (const float*)d_in[6];
    const float* b_ih     = (const float*)d_in[7];
    const float* b_hh     = (const float*)d_in[8];
    const float* conv_w   = (const float*)d_in[9];
    const float* conv_b   = (const float*)d_in[10];
    float* out = (float*)d_out;

    float *h, *hs, *gi, *gh, *wc, *whr, *cwr;
    cudaGetSymbolAddress((void**)&h,   g_h);
    cudaGetSymbolAddress((void**)&hs,  g_hs);
    cudaGetSymbolAddress((void**)&gi,  g_gi);
    cudaGetSymbolAddress((void**)&gh,  g_gh);
    cudaGetSymbolAddress((void**)&wc,  g_wc);
    cudaGetSymbolAddress((void**)&whr, g_whr);
    cudaGetSymbolAddress((void**)&cwr, g_cwr);

    static int smem_set = 0;
    if (!smem_set) {
        cudaFuncSetAttribute(gemm_mma_kernel,
                             cudaFuncAttributeMaxDynamicSharedMemorySize, SMEM_BYTES);
        smem_set = 1;
    }

    const int MT = NP / 128;                       // 391
    const dim3 grid_576(F3 / 64, MT);              // 9 x 391
    const dim3 grid_100((NCLS2 + 63) / 64, MT);    // 2 x 391
    const int gate_grid = (N_NODES * 48 + 255) / 256;

    // ---- setup (GEMM is launch #4 so ncu captures it) ----
    embed_gather_kernel<<<N_NODES, FDIM>>>(prop_ids, embed);                    // 1
    fold_kernel<<<F3, FDIM>>>(W_ih, W_edge);                                    // 2
    round_w_kernel<<<F3 + NCLS2, FDIM>>>(W_hh, conv_w);                         // 3
    gemm_mma_kernel<<<grid_576, 256, SMEM_BYTES>>>(h, whr, b_hh, gh, F3, NP, F3, 0); // 4: step-1 gh
    zero_deg_kernel<<<(NP + 255) / 256, 256>>>();                               // 5
    csr_count_kernel<<<(N_EDGES + 255) / 256, 256>>>(dst);                      // 6
    scan_kernel<<<1, 1024>>>();                                                 // 7
    csr_fill_kernel<<<(N_EDGES + 255) / 256, 256>>>(src, dst);                  // 8

    // ---- step 1 (gh already computed) ----
    gather_kernel<<<NP / 4, 192>>>();
    gemm_mma_kernel<<<grid_576, 256, SMEM_BYTES>>>(hs, wc, b_ih, gi, F3, NP, F3, 0);
    gate_kernel<<<gate_grid, 256>>>();

    // ---- steps 2..6 ----
    for (int step = 2; step <= STEP_MAX; ++step) {
        gather_kernel<<<NP / 4, 192>>>();
        gemm_mma_kernel<<<grid_576, 256, SMEM_BYTES>>>(h,  whr, b_hh, gh, F3, NP, F3, 0);
        gemm_mma_kernel<<<grid_576, 256, SMEM_BYTES>>>(hs, wc,  b_ih, gi, F3, NP, F3, 0);
        gate_kernel<<<gate_grid, 256>>>();
        int s = step - STEP_MIN;
        gemm_mma_kernel<<<grid_100, 256, SMEM_BYTES>>>(h, cwr, conv_b, out + s * NCLS2,
                                                       NCLS2, N_NODES, 5 * NCLS2, 1);
    }
}

// round 7
// speedup vs baseline: 1.2306x; 1.0791x over previous
#include <cuda_runtime.h>
#include <math.h>
#include <stdint.h>

#define N_NODES 50000
#define NP      50048              // padded to 391*128
#define N_EDGES 800000
#define EMBED_DIM 64
#define N_PROPS 3
#define FDIM 192
#define F3 576
#define NCLS2 100
#define STEP_MIN 2
#define STEP_MAX 6

// ---------------- device scratch ----------------
__device__ float g_h  [(size_t)NP * FDIM];
__device__ float g_hs [(size_t)NP * FDIM];
__device__ float g_gi [(size_t)NP * F3];
__device__ float g_gh [(size_t)NP * F3];
__device__ float g_wc [(size_t)F3 * FDIM];
__device__ float g_whr[(size_t)F3 * FDIM];
__device__ float g_cwr[(size_t)NCLS2 * FDIM];
__device__ int   g_deg[NP];
__device__ int   g_rowp[NP + 1];
__device__ int   g_cursor[NP];
__device__ int   g_csr[N_EDGES];

// RN-round fp32 -> tf32-representable fp32
__device__ __forceinline__ float rtf32(float x) {
    uint32_t u = __float_as_uint(x);
    u = (u + 0xfffu + ((u >> 13) & 1u)) & 0xFFFFE000u;
    return __uint_as_float(u);
}

// ================= embedding gather (tf32-rounded) =================
__global__ void embed_gather_kernel(const int* __restrict__ prop_ids,
                                    const float* __restrict__ table) {
    int n = blockIdx.x;
    int f = threadIdx.x;
    int p = f >> 6;
    int e = f & 63;
    int id = prop_ids[n * N_PROPS + p];
    g_h[(size_t)n * FDIM + f] = rtf32(table[(size_t)id * EMBED_DIM + e]);
}

// ================= W_c = round(W_ih @ W_edge) =================
__global__ void fold_kernel(const float* __restrict__ W_ih,
                            const float* __restrict__ W_edge) {
    int i = blockIdx.x;
    int j = threadIdx.x;
    float s = 0.f;
    #pragma unroll 8
    for (int k = 0; k < FDIM; ++k)
        s = fmaf(__ldg(W_ih + i * FDIM + k), __ldg(W_edge + k * FDIM + j), s);
    g_wc[(size_t)i * FDIM + j] = rtf32(s);
}

// ================= round W_hh / conv_w into scratch =================
__global__ void round_w_kernel(const float* __restrict__ W_hh,
                               const float* __restrict__ conv_w) {
    int i = blockIdx.x;
    int j = threadIdx.x;
    if (i < F3)
        g_whr[(size_t)i * FDIM + j] = rtf32(__ldg(W_hh + (size_t)i * FDIM + j));
    else
        g_cwr[(size_t)(i - F3) * FDIM + j] = rtf32(__ldg(conv_w + (size_t)(i - F3) * FDIM + j));
}

// ================= CSR build =================
__global__ void zero_deg_kernel() {
    int i = blockIdx.x * 256 + threadIdx.x;
    if (i < NP) g_deg[i] = 0;
}
__global__ void csr_count_kernel(const int* __restrict__ dst) {
    int e = blockIdx.x * 256 + threadIdx.x;
    if (e < N_EDGES) atomicAdd(&g_deg[dst[e]], 1);
}
__global__ __launch_bounds__(1024) void scan_kernel() {
    __shared__ int part[1024];
    const int CH = 49;
    int t = threadIdx.x;
    int base = t * CH;
    int s = 0;
    #pragma unroll 7
    for (int i = 0; i < CH; ++i) {
        int idx = base + i;
        if (idx < NP) s += g_deg[idx];
    }
    part[t] = s;
    __syncthreads();
    for (int off = 1; off < 1024; off <<= 1) {
        int v = part[t];
        int u = (t >= off) ? part[t - off] : 0;
        __syncthreads();
        part[t] = v + u;
        __syncthreads();
    }
    int run = (t > 0) ? part[t - 1] : 0;
    for (int i = 0; i < CH; ++i) {
        int idx = base + i;
        if (idx < NP) {
            g_rowp[idx]   = run;
            g_cursor[idx] = run;
            run += g_deg[idx];
        }
    }
    if (t == 0) g_rowp[NP] = N_EDGES;
}
__global__ void csr_fill_kernel(const int* __restrict__ src,
                                const int* __restrict__ dst) {
    int e = blockIdx.x * 256 + threadIdx.x;
    if (e < N_EDGES) {
        int p = atomicAdd(&g_cursor[dst[e]], 1);
        g_csr[p] = src[e];
    }
}

// ================= aggregation (tf32-rounded output) =================
__global__ __launch_bounds__(192) void gather_kernel() {
    int g = threadIdx.x / 48;
    int c = threadIdx.x % 48;
    int n = blockIdx.x * 4 + g;
    int beg = __ldg(&g_rowp[n]);
    int end = __ldg(&g_rowp[n + 1]);
    const float4* h4 = reinterpret_cast<const float4*>(g_h);
    float4 v = make_float4(0.f, 0.f, 0.f, 0.f);
    int i = beg;
    for (; i + 2 <= end; i += 2) {
        int s0 = __ldg(&g_csr[i]);
        int s1 = __ldg(&g_csr[i + 1]);
        float4 a = h4[(size_t)s0 * 48 + c];
        float4 b = h4[(size_t)s1 * 48 + c];
        v.x += a.x + b.x; v.y += a.y + b.y;
        v.z += a.z + b.z; v.w += a.w + b.w;
    }
    if (i < end) {
        int s0 = __ldg(&g_csr[i]);
        float4 a = h4[(size_t)s0 * 48 + c];
        v.x += a.x; v.y += a.y; v.z += a.z; v.w += a.w;
    }
    v.x = rtf32(v.x); v.y = rtf32(v.y); v.z = rtf32(v.z); v.w = rtf32(v.w);
    reinterpret_cast<float4*>(g_hs)[(size_t)n * 48 + c] = v;
}

// ================= GRU gate fusion (tf32-rounded h) =================
__global__ void gate_kernel() {
    int idx = blockIdx.x * blockDim.x + threadIdx.x;
    if (idx >= N_NODES * 48) return;
    int n = idx / 48;
    int f4 = idx - n * 48;
    const float4* gi = reinterpret_cast<const float4*>(g_gi) + (size_t)n * 144 + f4;
    const float4* gh = reinterpret_cast<const float4*>(g_gh) + (size_t)n * 144 + f4;
    float4 gir = gi[0],  ghr = gh[0];
    float4 giz = gi[48], ghz = gh[48];
    float4 gin = gi[96], ghn = gh[96];
    float4* hp = reinterpret_cast<float4*>(g_h) + (size_t)n * 48 + f4;
    float4 h = *hp, o;
    #define GATE1(X) { \
        float r = 1.f / (1.f + expf(-(gir.X + ghr.X))); \
        float z = 1.f / (1.f + expf(-(giz.X + ghz.X))); \
        float nn = tanhf(gin.X + r * ghn.X); \
        o.X = rtf32((1.f - z) * nn + z * h.X); }
    GATE1(x) GATE1(y) GATE1(z) GATE1(w)
    #undef GATE1
    *hp = o;
}

// ================= mma.sync tf32 GEMM, cp.async 2-stage, z-fused =================
// z = blockIdx.z selects (A,B,bias,C) tuple 0 or 1.
// CTA tile 128x64, 8 warps (4x2), warp tile 32x32 (2x4 m16n8k8 atoms).
// BK=32 slab, 2-stage cp.async (55 KB smem -> 3 CTAs/SM), SA=36 conflict-free.

#define SA   36
#define AST  (128 * SA)
#define BST  (64 * SA)
#define STG  (AST + BST)
#define SMEM_BYTES (2 * STG * 4)

__device__ __forceinline__ void mma_tf32(float* c, const uint32_t* a, const uint32_t* b) {
    asm volatile(
        "mma.sync.aligned.m16n8k8.row.col.f32.tf32.tf32.f32 "
        "{%0,%1,%2,%3}, {%4,%5,%6,%7}, {%8,%9}, {%0,%1,%2,%3};"
        : "+f"(c[0]), "+f"(c[1]), "+f"(c[2]), "+f"(c[3])
        : "r"(a[0]), "r"(a[1]), "r"(a[2]), "r"(a[3]), "r"(b[0]), "r"(b[1]));
}
__device__ __forceinline__ void cp16(uint32_t saddr, const float* g, int pred) {
    int sz = pred ? 16 : 0;
    asm volatile("cp.async.cg.shared.global [%0], [%1], 16, %2;"
                 :: "r"(saddr), "l"(g), "r"(sz) : "memory");
}

__global__ __launch_bounds__(256)
void gemm_mma_kernel(const float* __restrict__ A0, const float* __restrict__ A1,
                     const float* __restrict__ B0, const float* __restrict__ B1,
                     const float* __restrict__ bias0, const float* __restrict__ bias1,
                     float* __restrict__ C0, float* __restrict__ C1,
                     int Ntot, int Mstore, int ldc, int act) {
    extern __shared__ float sm[];
    uint32_t smb;
    asm("{ .reg .u64 t; cvta.to.shared.u64 t, %1; cvt.u32.u64 %0, t; }"
        : "=r"(smb) : "l"(sm));

    int z = blockIdx.z;
    const float* A    = z ? A1    : A0;
    const float* B    = z ? B1    : B0;
    const float* bias = z ? bias1 : bias0;
    float*       C    = z ? C1    : C0;

    int tid  = threadIdx.x;
    int lane = tid & 31, wid = tid >> 5;
    int wr = wid & 3, wc2 = wid >> 2;
    int lr = lane >> 2, lc = lane & 3;
    int m0 = blockIdx.y * 128;
    int n0 = blockIdx.x * 64;

    int a_row[4], a_c4[4], b_row[2], b_c4[2];
    #pragma unroll
    for (int i = 0; i < 4; ++i) { int it = i * 256 + tid; a_row[i] = it >> 3; a_c4[i] = it & 7; }
    #pragma unroll
    for (int i = 0; i < 2; ++i) { int it = i * 256 + tid; b_row[i] = it >> 3; b_c4[i] = it & 7; }

    #define PREFETCH(s, st) { \
        uint32_t sa_ = smb + (st) * (STG * 4); \
        _Pragma("unroll") \
        for (int i = 0; i < 4; ++i) \
            cp16(sa_ + (a_row[i] * SA + a_c4[i] * 4) * 4, \
                 A + (size_t)(m0 + a_row[i]) * FDIM + (s) * 32 + a_c4[i] * 4, 1); \
        uint32_t sb_ = sa_ + AST * 4; \
        _Pragma("unroll") \
        for (int i = 0; i < 2; ++i) \
            cp16(sb_ + (b_row[i] * SA + b_c4[i] * 4) * 4, \
                 B + (size_t)(n0 + b_row[i]) * FDIM + (s) * 32 + b_c4[i] * 4, \
                 (n0 + b_row[i]) < Ntot); \
        asm volatile("cp.async.commit_group;" ::: "memory"); \
    }

    float acc[2][4][4];
    #pragma unroll
    for (int i = 0; i < 2; ++i)
        #pragma unroll
        for (int j = 0; j < 4; ++j)
            #pragma unroll
            for (int q = 0; q < 4; ++q) acc[i][j][q] = 0.f;

    PREFETCH(0, 0);

    #pragma unroll 1
    for (int s = 0; s < 6; ++s) {
        if (s + 1 < 6) {
            PREFETCH(s + 1, (s + 1) & 1);
            asm volatile("cp.async.wait_group 1;" ::: "memory");
        } else {
            asm volatile("cp.async.wait_group 0;" ::: "memory");
        }
        __syncthreads();

        const float* Asp = sm + (s & 1) * STG;
        const float* Bsp = Asp + AST;
        #pragma unroll
        for (int ks = 0; ks < 4; ++ks) {
            int kk = ks * 8 + lc;
            uint32_t a[2][4], b[4][2];
            #pragma unroll
            for (int ma = 0; ma < 2; ++ma) {
                int r = wr * 32 + ma * 16 + lr;
                a[ma][0] = __float_as_uint(Asp[r * SA + kk]);
                a[ma][1] = __float_as_uint(Asp[(r + 8) * SA + kk]);
                a[ma][2] = __float_as_uint(Asp[r * SA + kk + 4]);
                a[ma][3] = __float_as_uint(Asp[(r + 8) * SA + kk + 4]);
            }
            #pragma unroll
            for (int na = 0; na < 4; ++na) {
                int bn = wc2 * 32 + na * 8 + lr;
                b[na][0] = __float_as_uint(Bsp[bn * SA + kk]);
                b[na][1] = __float_as_uint(Bsp[bn * SA + kk + 4]);
            }
            #pragma unroll
            for (int ma = 0; ma < 2; ++ma)
                #pragma unroll
                for (int na = 0; na < 4; ++na)
                    mma_tf32(acc[ma][na], a[ma], b[na]);
        }
        __syncthreads();
    }

    // ---- epilogue ----
    #pragma unroll
    for (int ma = 0; ma < 2; ++ma) {
        #pragma unroll
        for (int na = 0; na < 4; ++na) {
            int row = m0 + wr * 32 + ma * 16 + lr;
            int col = n0 + wc2 * 32 + na * 8 + lc * 2;
            #pragma unroll
            for (int half = 0; half < 2; ++half) {
                int r = row + half * 8;
                if (r >= Mstore) continue;
                float v0 = acc[ma][na][half * 2 + 0];
                float v1 = acc[ma][na][half * 2 + 1];
                if (col + 1 < Ntot) {
                    v0 += __ldg(bias + col);
                    v1 += __ldg(bias + col + 1);
                    if (act) { v0 = 1.f / (1.f + expf(-v0)); v1 = 1.f / (1.f + expf(-v1)); }
                    *reinterpret_cast<float2*>(C + (size_t)r * ldc + col) = make_float2(v0, v1);
                } else if (col < Ntot) {
                    v0 += __ldg(bias + col);
                    if (act) v0 = 1.f / (1.f + expf(-v0));
                    C[(size_t)r * ldc + col] = v0;
                }
            }
        }
    }
}

// ================= launch =================
extern "C" void kernel_launch(void* const* d_in, const int* in_sizes, int n_in,
                              void* d_out, int out_size) {
    const int*   prop_ids = (const int*)d_in[0];
    const int*   src      = (const int*)d_in[1];
    const int*   dst      = (const int*)d_in[2];
    const float* embed    = (const float*)d_in[3];
    const float* W_edge   = (const float*)d_in[4];
    const float* W_ih     = (const float*)d_in[5];
    const float* W_hh     = (const float*)d_in[6];
    const float* b_ih     = (const float*)d_in[7];
    const float* b_hh     = (const float*)d_in[8];
    const float* conv_w   = (const float*)d_in[9];
    const float* conv_b   = (const float*)d_in[10];
    float* out = (float*)d_out;

    float *h, *hs, *gi, *gh, *wc, *whr, *cwr;
    cudaGetSymbolAddress((void**)&h,   g_h);
    cudaGetSymbolAddress((void**)&hs,  g_hs);
    cudaGetSymbolAddress((void**)&gi,  g_gi);
    cudaGetSymbolAddress((void**)&gh,  g_gh);
    cudaGetSymbolAddress((void**)&wc,  g_wc);
    cudaGetSymbolAddress((void**)&whr, g_whr);
    cudaGetSymbolAddress((void**)&cwr, g_cwr);

    static int smem_set = 0;
    if (!smem_set) {
        cudaFuncSetAttribute(gemm_mma_kernel,
                             cudaFuncAttributeMaxDynamicSharedMemorySize, SMEM_BYTES);
        smem_set = 1;
    }

    const int MT = NP / 128;                        // 391
    const dim3 grid_one(F3 / 64, MT, 1);            // single 576-GEMM
    const dim3 grid_two(F3 / 64, MT, 2);            // gi + gh fused
    const dim3 grid_cls((NCLS2 + 63) / 64, MT, 1);
    const int gate_grid = (N_NODES * 48 + 255) / 256;

    // ---- setup (GEMM is launch #4 so ncu captures it) ----
    embed_gather_kernel<<<N_NODES, FDIM>>>(prop_ids, embed);                    // 1
    fold_kernel<<<F3, FDIM>>>(W_ih, W_edge);                                    // 2
    round_w_kernel<<<F3 + NCLS2, FDIM>>>(W_hh, conv_w);                         // 3
    gemm_mma_kernel<<<grid_one, 256, SMEM_BYTES>>>(h, h, whr, whr, b_hh, b_hh,
                                                   gh, gh, F3, NP, F3, 0);      // 4: step-1 gh
    zero_deg_kernel<<<(NP + 255) / 256, 256>>>();                               // 5
    csr_count_kernel<<<(N_EDGES + 255) / 256, 256>>>(dst);                      // 6
    scan_kernel<<<1, 1024>>>();                                                 // 7
    csr_fill_kernel<<<(N_EDGES + 255) / 256, 256>>>(src, dst);                  // 8

    // ---- step 1 (gh already computed) ----
    gather_kernel<<<NP / 4, 192>>>();
    gemm_mma_kernel<<<grid_one, 256, SMEM_BYTES>>>(hs, hs, wc, wc, b_ih, b_ih,
                                                   gi, gi, F3, NP, F3, 0);
    gate_kernel<<<gate_grid, 256>>>();

    // ---- steps 2..6 ----
    for (int step = 2; step <= STEP_MAX; ++step) {
        gather_kernel<<<NP / 4, 192>>>();
        gemm_mma_kernel<<<grid_two, 256, SMEM_BYTES>>>(hs, h, wc, whr, b_ih, b_hh,
                                                       gi, gh, F3, NP, F3, 0);
        gate_kernel<<<gate_grid, 256>>>();
        int s = step - STEP_MIN;
        gemm_mma_kernel<<<grid_cls, 256, SMEM_BYTES>>>(h, h, cwr, cwr, conv_b, conv_b,
                                                       out + s * NCLS2, out + s * NCLS2,
                                                       NCLS2, N_NODES, 5 * NCLS2, 1);
    }
}

// round 8
// speedup vs baseline: 1.2634x; 1.0266x over previous
#include <cuda_runtime.h>
#include <math.h>
#include <stdint.h>

#define N_NODES 50000
#define NP      50176              // padded to 196*256
#define N_EDGES 800000
#define EMBED_DIM 64
#define N_PROPS 3
#define FDIM 192
#define F3 576
#define NCLS2 100
#define STEP_MIN 2
#define STEP_MAX 6

// ---------------- device scratch ----------------
__device__ float g_h  [(size_t)NP * FDIM];
__device__ float g_hs [(size_t)NP * FDIM];
__device__ float g_gi [(size_t)NP * F3];
__device__ float g_gh [(size_t)NP * F3];
__device__ float g_wc [(size_t)F3 * FDIM];
__device__ float g_whr[(size_t)F3 * FDIM];
__device__ float g_cwr[(size_t)NCLS2 * FDIM];
__device__ int   g_deg[NP];
__device__ int   g_rowp[NP + 1];
__device__ int   g_cursor[NP];
__device__ int   g_csr[N_EDGES];

// RN-round fp32 -> tf32-representable fp32
__device__ __forceinline__ float rtf32(float x) {
    uint32_t u = __float_as_uint(x);
    u = (u + 0xfffu + ((u >> 13) & 1u)) & 0xFFFFE000u;
    return __uint_as_float(u);
}

// ================= embedding gather (tf32-rounded) =================
__global__ void embed_gather_kernel(const int* __restrict__ prop_ids,
                                    const float* __restrict__ table) {
    int n = blockIdx.x;
    int f = threadIdx.x;
    int p = f >> 6;
    int e = f & 63;
    int id = prop_ids[n * N_PROPS + p];
    g_h[(size_t)n * FDIM + f] = rtf32(table[(size_t)id * EMBED_DIM + e]);
}

// ================= W_c = round(W_ih @ W_edge) =================
__global__ void fold_kernel(const float* __restrict__ W_ih,
                            const float* __restrict__ W_edge) {
    int i = blockIdx.x;
    int j = threadIdx.x;
    float s = 0.f;
    #pragma unroll 8
    for (int k = 0; k < FDIM; ++k)
        s = fmaf(__ldg(W_ih + i * FDIM + k), __ldg(W_edge + k * FDIM + j), s);
    g_wc[(size_t)i * FDIM + j] = rtf32(s);
}

// ================= round W_hh / conv_w into scratch =================
__global__ void round_w_kernel(const float* __restrict__ W_hh,
                               const float* __restrict__ conv_w) {
    int i = blockIdx.x;
    int j = threadIdx.x;
    if (i < F3)
        g_whr[(size_t)i * FDIM + j] = rtf32(__ldg(W_hh + (size_t)i * FDIM + j));
    else
        g_cwr[(size_t)(i - F3) * FDIM + j] = rtf32(__ldg(conv_w + (size_t)(i - F3) * FDIM + j));
}

// ================= CSR build =================
__global__ void zero_deg_kernel() {
    int i = blockIdx.x * 256 + threadIdx.x;
    if (i < NP) g_deg[i] = 0;
}
__global__ void csr_count_kernel(const int* __restrict__ dst) {
    int e = blockIdx.x * 256 + threadIdx.x;
    if (e < N_EDGES) atomicAdd(&g_deg[dst[e]], 1);
}
__global__ __launch_bounds__(1024) void scan_kernel() {
    __shared__ int part[1024];
    const int CH = 49;                 // 1024*49 = 50176 = NP
    int t = threadIdx.x;
    int base = t * CH;
    int s = 0;
    #pragma unroll 7
    for (int i = 0; i < CH; ++i) {
        int idx = base + i;
        if (idx < NP) s += g_deg[idx];
    }
    part[t] = s;
    __syncthreads();
    for (int off = 1; off < 1024; off <<= 1) {
        int v = part[t];
        int u = (t >= off) ? part[t - off] : 0;
        __syncthreads();
        part[t] = v + u;
        __syncthreads();
    }
    int run = (t > 0) ? part[t - 1] : 0;
    for (int i = 0; i < CH; ++i) {
        int idx = base + i;
        if (idx < NP) {
            g_rowp[idx]   = run;
            g_cursor[idx] = run;
            run += g_deg[idx];
        }
    }
    if (t == 0) g_rowp[NP] = N_EDGES;
}
__global__ void csr_fill_kernel(const int* __restrict__ src,
                                const int* __restrict__ dst) {
    int e = blockIdx.x * 256 + threadIdx.x;
    if (e < N_EDGES) {
        int p = atomicAdd(&g_cursor[dst[e]], 1);
        g_csr[p] = src[e];
    }
}

// ================= aggregation (tf32-rounded output) =================
__global__ __launch_bounds__(192) void gather_kernel() {
    int g = threadIdx.x / 48;
    int c = threadIdx.x % 48;
    int n = blockIdx.x * 4 + g;
    int beg = __ldg(&g_rowp[n]);
    int end = __ldg(&g_rowp[n + 1]);
    const float4* h4 = reinterpret_cast<const float4*>(g_h);
    float4 v = make_float4(0.f, 0.f, 0.f, 0.f);
    int i = beg;
    for (; i + 2 <= end; i += 2) {
        int s0 = __ldg(&g_csr[i]);
        int s1 = __ldg(&g_csr[i + 1]);
        float4 a = h4[(size_t)s0 * 48 + c];
        float4 b = h4[(size_t)s1 * 48 + c];
        v.x += a.x + b.x; v.y += a.y + b.y;
        v.z += a.z + b.z; v.w += a.w + b.w;
    }
    if (i < end) {
        int s0 = __ldg(&g_csr[i]);
        float4 a = h4[(size_t)s0 * 48 + c];
        v.x += a.x; v.y += a.y; v.z += a.z; v.w += a.w;
    }
    v.x = rtf32(v.x); v.y = rtf32(v.y); v.z = rtf32(v.z); v.w = rtf32(v.w);
    reinterpret_cast<float4*>(g_hs)[(size_t)n * 48 + c] = v;
}

// ================= GRU gate fusion (tf32-rounded h) =================
__global__ void gate_kernel() {
    int idx = blockIdx.x * blockDim.x + threadIdx.x;
    if (idx >= N_NODES * 48) return;
    int n = idx / 48;
    int f4 = idx - n * 48;
    const float4* gi = reinterpret_cast<const float4*>(g_gi) + (size_t)n * 144 + f4;
    const float4* gh = reinterpret_cast<const float4*>(g_gh) + (size_t)n * 144 + f4;
    float4 gir = gi[0],  ghr = gh[0];
    float4 giz = gi[48], ghz = gh[48];
    float4 gin = gi[96], ghn = gh[96];
    float4* hp = reinterpret_cast<float4*>(g_h) + (size_t)n * 48 + f4;
    float4 h = *hp, o;
    #define GATE1(X) { \
        float r = 1.f / (1.f + expf(-(gir.X + ghr.X))); \
        float z = 1.f / (1.f + expf(-(giz.X + ghz.X))); \
        float nn = tanhf(gin.X + r * ghn.X); \
        o.X = rtf32((1.f - z) * nn + z * h.X); }
    GATE1(x) GATE1(y) GATE1(z) GATE1(w)
    #undef GATE1
    *hp = o;
}

// ================= mma.sync tf32 GEMM, templated warp M-tile =================
// z = blockIdx.z selects (A,B,bias,C) tuple 0 or 1.
// Warps 4x2; warp tile (MA*16) x 32; CTA tile (MA*64) x 64.
// MA=4: 256x64 CTA, 96 LDS : 64 HMMA per slab (1.5:1). MA=2: 128x64.
// BK=32 slab, 2-stage cp.async, SA=36 conflict-free.

#define SA 36

__device__ __forceinline__ void mma_tf32(float* c, const uint32_t* a, const uint32_t* b) {
    asm volatile(
        "mma.sync.aligned.m16n8k8.row.col.f32.tf32.tf32.f32 "
        "{%0,%1,%2,%3}, {%4,%5,%6,%7}, {%8,%9}, {%0,%1,%2,%3};"
        : "+f"(c[0]), "+f"(c[1]), "+f"(c[2]), "+f"(c[3])
        : "r"(a[0]), "r"(a[1]), "r"(a[2]), "r"(a[3]), "r"(b[0]), "r"(b[1]));
}
__device__ __forceinline__ void cp16(uint32_t saddr, const float* g, int pred) {
    int sz = pred ? 16 : 0;
    asm volatile("cp.async.cg.shared.global [%0], [%1], 16, %2;"
                 :: "r"(saddr), "l"(g), "r"(sz) : "memory");
}

template <int MA>
__global__ __launch_bounds__(256)
void gemm_mma_kernel(const float* __restrict__ A0, const float* __restrict__ A1,
                     const float* __restrict__ B0, const float* __restrict__ B1,
                     const float* __restrict__ bias0, const float* __restrict__ bias1,
                     float* __restrict__ C0, float* __restrict__ C1,
                     int Ntot, int Mstore, int ldc, int act) {
    constexpr int AROWS = MA * 64;
    constexpr int AST   = AROWS * SA;
    constexpr int BST   = 64 * SA;
    constexpr int STG   = AST + BST;

    extern __shared__ float sm[];
    uint32_t smb;
    asm("{ .reg .u64 t; cvta.to.shared.u64 t, %1; cvt.u32.u64 %0, t; }"
        : "=r"(smb) : "l"(sm));

    int z = blockIdx.z;
    const float* A    = z ? A1    : A0;
    const float* B    = z ? B1    : B0;
    const float* bias = z ? bias1 : bias0;
    float*       C    = z ? C1    : C0;

    int tid  = threadIdx.x;
    int lane = tid & 31, wid = tid >> 5;
    int wr = wid & 3, wc2 = wid >> 2;
    int lr = lane >> 2, lc = lane & 3;
    int m0 = blockIdx.y * AROWS;
    int n0 = blockIdx.x * 64;

    int a_row[2 * MA], a_c4[2 * MA], b_row[2], b_c4[2];
    #pragma unroll
    for (int i = 0; i < 2 * MA; ++i) { int it = i * 256 + tid; a_row[i] = it >> 3; a_c4[i] = it & 7; }
    #pragma unroll
    for (int i = 0; i < 2; ++i) { int it = i * 256 + tid; b_row[i] = it >> 3; b_c4[i] = it & 7; }

    #define PREFETCH(s, st) { \
        uint32_t sa_ = smb + (st) * (STG * 4); \
        _Pragma("unroll") \
        for (int i = 0; i < 2 * MA; ++i) \
            cp16(sa_ + (a_row[i] * SA + a_c4[i] * 4) * 4, \
                 A + (size_t)(m0 + a_row[i]) * FDIM + (s) * 32 + a_c4[i] * 4, 1); \
        uint32_t sb_ = sa_ + AST * 4; \
        _Pragma("unroll") \
        for (int i = 0; i < 2; ++i) \
            cp16(sb_ + (b_row[i] * SA + b_c4[i] * 4) * 4, \
                 B + (size_t)(n0 + b_row[i]) * FDIM + (s) * 32 + b_c4[i] * 4, \
                 (n0 + b_row[i]) < Ntot); \
        asm volatile("cp.async.commit_group;" ::: "memory"); \
    }

    float acc[MA][4][4];
    #pragma unroll
    for (int i = 0; i < MA; ++i)
        #pragma unroll
        for (int j = 0; j < 4; ++j)
            #pragma unroll
            for (int q = 0; q < 4; ++q) acc[i][j][q] = 0.f;

    PREFETCH(0, 0);

    #pragma unroll 1
    for (int s = 0; s < 6; ++s) {
        if (s + 1 < 6) {
            PREFETCH(s + 1, (s + 1) & 1);
            asm volatile("cp.async.wait_group 1;" ::: "memory");
        } else {
            asm volatile("cp.async.wait_group 0;" ::: "memory");
        }
        __syncthreads();

        const float* Asp = sm + (s & 1) * STG;
        const float* Bsp = Asp + AST;
        #pragma unroll
        for (int ks = 0; ks < 4; ++ks) {
            int kk = ks * 8 + lc;
            uint32_t a[MA][4], b[4][2];
            #pragma unroll
            for (int ma = 0; ma < MA; ++ma) {
                int r = wr * (MA * 16) + ma * 16 + lr;
                a[ma][0] = __float_as_uint(Asp[r * SA + kk]);
                a[ma][1] = __float_as_uint(Asp[(r + 8) * SA + kk]);
                a[ma][2] = __float_as_uint(Asp[r * SA + kk + 4]);
                a[ma][3] = __float_as_uint(Asp[(r + 8) * SA + kk + 4]);
            }
            #pragma unroll
            for (int na = 0; na < 4; ++na) {
                int bn = wc2 * 32 + na * 8 + lr;
                b[na][0] = __float_as_uint(Bsp[bn * SA + kk]);
                b[na][1] = __float_as_uint(Bsp[bn * SA + kk + 4]);
            }
            #pragma unroll
            for (int ma = 0; ma < MA; ++ma)
                #pragma unroll
                for (int na = 0; na < 4; ++na)
                    mma_tf32(acc[ma][na], a[ma], b[na]);
        }
        __syncthreads();
    }

    // ---- epilogue ----
    #pragma unroll
    for (int ma = 0; ma < MA; ++ma) {
        #pragma unroll
        for (int na = 0; na < 4; ++na) {
            int row = m0 + wr * (MA * 16) + ma * 16 + lr;
            int col = n0 + wc2 * 32 + na * 8 + lc * 2;
            #pragma unroll
            for (int half = 0; half < 2; ++half) {
                int r = row + half * 8;
                if (r >= Mstore) continue;
                float v0 = acc[ma][na][half * 2 + 0];
                float v1 = acc[ma][na][half * 2 + 1];
                if (col + 1 < Ntot) {
                    v0 += __ldg(bias + col);
                    v1 += __ldg(bias + col + 1);
                    if (act) { v0 = 1.f / (1.f + expf(-v0)); v1 = 1.f / (1.f + expf(-v1)); }
                    *reinterpret_cast<float2*>(C + (size_t)r * ldc + col) = make_float2(v0, v1);
                } else if (col < Ntot) {
                    v0 += __ldg(bias + col);
                    if (act) v0 = 1.f / (1.f + expf(-v0));
                    C[(size_t)r * ldc + col] = v0;
                }
            }
        }
    }
    #undef PREFETCH
}

// ================= launch =================
extern "C" void kernel_launch(void* const* d_in, const int* in_sizes, int n_in,
                              void* d_out, int out_size) {
    const int*   prop_ids = (const int*)d_in[0];
    const int*   src      = (const int*)d_in[1];
    const int*   dst      = (const int*)d_in[2];
    const float* embed    = (const float*)d_in[3];
    const float* W_edge   = (const float*)d_in[4];
    const float* W_ih     = (const float*)d_in[5];
    const float* W_hh     = (const float*)d_in[6];
    const float* b_ih     = (const float*)d_in[7];
    const float* b_hh     = (const float*)d_in[8];
    const float* conv_w   = (const float*)d_in[9];
    const float* conv_b   = (const float*)d_in[10];
    float* out = (float*)d_out;

    float *h, *hs, *gi, *gh, *wc, *whr, *cwr;
    cudaGetSymbolAddress((void**)&h,   g_h);
    cudaGetSymbolAddress((void**)&hs,  g_hs);
    cudaGetSymbolAddress((void**)&gi,  g_gi);
    cudaGetSymbolAddress((void**)&gh,  g_gh);
    cudaGetSymbolAddress((void**)&wc,  g_wc);
    cudaGetSymbolAddress((void**)&whr, g_whr);
    cudaGetSymbolAddress((void**)&cwr, g_cwr);

    const int SMEM2 = 2 * (128 * SA + 64 * SA) * 4;   // MA=2: 55296 B
    const int SMEM4 = 2 * (256 * SA + 64 * SA) * 4;   // MA=4: 92160 B

    static int smem_set = 0;
    if (!smem_set) {
        cudaFuncSetAttribute(gemm_mma_kernel<2>,
                             cudaFuncAttributeMaxDynamicSharedMemorySize, SMEM2);
        cudaFuncSetAttribute(gemm_mma_kernel<4>,
                             cudaFuncAttributeMaxDynamicSharedMemorySize, SMEM4);
        smem_set = 1;
    }

    const int MT4 = NP / 256;                       // 196
    const int MT2 = NP / 128;                       // 392
    const dim3 grid_one(F3 / 64, MT4, 1);           // single 576-GEMM, 256-row tiles
    const dim3 grid_two(F3 / 64, MT4, 2);           // gi + gh fused
    const dim3 grid_cls((NCLS2 + 63) / 64, MT2, 1); // class GEMM, 128-row tiles
    const int gate_grid = (N_NODES * 48 + 255) / 256;

    // ---- setup (big GEMM is launch #4 so ncu captures it) ----
    embed_gather_kernel<<<N_NODES, FDIM>>>(prop_ids, embed);                    // 1
    fold_kernel<<<F3, FDIM>>>(W_ih, W_edge);                                    // 2
    round_w_kernel<<<F3 + NCLS2, FDIM>>>(W_hh, conv_w);                         // 3
    gemm_mma_kernel<4><<<grid_one, 256, SMEM4>>>(h, h, whr, whr, b_hh, b_hh,
                                                 gh, gh, F3, NP, F3, 0);        // 4: step-1 gh
    zero_deg_kernel<<<(NP + 255) / 256, 256>>>();                               // 5
    csr_count_kernel<<<(N_EDGES + 255) / 256, 256>>>(dst);                      // 6
    scan_kernel<<<1, 1024>>>();                                                 // 7
    csr_fill_kernel<<<(N_EDGES + 255) / 256, 256>>>(src, dst);                  // 8

    // ---- step 1 (gh already computed) ----
    gather_kernel<<<NP / 4, 192>>>();
    gemm_mma_kernel<4><<<grid_one, 256, SMEM4>>>(hs, hs, wc, wc, b_ih, b_ih,
                                                 gi, gi, F3, NP, F3, 0);
    gate_kernel<<<gate_grid, 256>>>();

    // ---- steps 2..6 ----
    for (int step = 2; step <= STEP_MAX; ++step) {
        gather_kernel<<<NP / 4, 192>>>();
        gemm_mma_kernel<4><<<grid_two, 256, SMEM4>>>(hs, h, wc, whr, b_ih, b_hh,
                                                     gi, gh, F3, NP, F3, 0);
        gate_kernel<<<gate_grid, 256>>>();
        int s = step - STEP_MIN;
        gemm_mma_kernel<2><<<grid_cls, 256, SMEM2>>>(h, h, cwr, cwr, conv_b, conv_b,
                                                     out + s * NCLS2, out + s * NCLS2,
                                                     NCLS2, N_NODES, 5 * NCLS2, 1);
    }
}

// round 9
// speedup vs baseline: 1.2966x; 1.0263x over previous
#include <cuda_runtime.h>
#include <math.h>
#include <stdint.h>

#define N_NODES 50000
#define NP      50176              // padded to 196*256
#define N_EDGES 800000
#define EMBED_DIM 64
#define N_PROPS 3
#define FDIM 192
#define F3 576
#define NCLS2 100
#define STEP_MIN 2
#define STEP_MAX 6

// ---------------- device scratch ----------------
__device__ float g_h  [(size_t)NP * FDIM];
__device__ float g_hs [(size_t)NP * FDIM];
__device__ float g_gi [(size_t)NP * F3];
__device__ float g_gh [(size_t)NP * F3];
__device__ float g_wc [(size_t)F3 * FDIM];
__device__ float g_whr[(size_t)F3 * FDIM];
__device__ float g_cwr[(size_t)NCLS2 * FDIM];
__device__ int   g_deg[NP];
__device__ int   g_rowp[NP + 1];
__device__ int   g_cursor[NP];
__device__ int   g_csr[N_EDGES];

// RN-round fp32 -> tf32-representable fp32
__device__ __forceinline__ float rtf32(float x) {
    uint32_t u = __float_as_uint(x);
    u = (u + 0xfffu + ((u >> 13) & 1u)) & 0xFFFFE000u;
    return __uint_as_float(u);
}

// ================= embedding gather (tf32-rounded) =================
__global__ void embed_gather_kernel(const int* __restrict__ prop_ids,
                                    const float* __restrict__ table) {
    int n = blockIdx.x;
    int f = threadIdx.x;
    int p = f >> 6;
    int e = f & 63;
    int id = prop_ids[n * N_PROPS + p];
    g_h[(size_t)n * FDIM + f] = rtf32(table[(size_t)id * EMBED_DIM + e]);
}

// ================= W_c = round(W_ih @ W_edge) =================
__global__ void fold_kernel(const float* __restrict__ W_ih,
                            const float* __restrict__ W_edge) {
    int i = blockIdx.x;
    int j = threadIdx.x;
    float s = 0.f;
    #pragma unroll 8
    for (int k = 0; k < FDIM; ++k)
        s = fmaf(__ldg(W_ih + i * FDIM + k), __ldg(W_edge + k * FDIM + j), s);
    g_wc[(size_t)i * FDIM + j] = rtf32(s);
}

// ================= round W_hh / conv_w into scratch =================
__global__ void round_w_kernel(const float* __restrict__ W_hh,
                               const float* __restrict__ conv_w) {
    int i = blockIdx.x;
    int j = threadIdx.x;
    if (i < F3)
        g_whr[(size_t)i * FDIM + j] = rtf32(__ldg(W_hh + (size_t)i * FDIM + j));
    else
        g_cwr[(size_t)(i - F3) * FDIM + j] = rtf32(__ldg(conv_w + (size_t)(i - F3) * FDIM + j));
}

// ================= CSR build =================
__global__ void zero_deg_kernel() {
    int i = blockIdx.x * 256 + threadIdx.x;
    if (i < NP) g_deg[i] = 0;
}
__global__ void csr_count_kernel(const int* __restrict__ dst) {
    int e = blockIdx.x * 256 + threadIdx.x;
    if (e < N_EDGES) atomicAdd(&g_deg[dst[e]], 1);
}
__global__ __launch_bounds__(1024) void scan_kernel() {
    __shared__ int part[1024];
    const int CH = 49;                 // 1024*49 = 50176 = NP
    int t = threadIdx.x;
    int base = t * CH;
    int s = 0;
    #pragma unroll 7
    for (int i = 0; i < CH; ++i) {
        int idx = base + i;
        if (idx < NP) s += g_deg[idx];
    }
    part[t] = s;
    __syncthreads();
    for (int off = 1; off < 1024; off <<= 1) {
        int v = part[t];
        int u = (t >= off) ? part[t - off] : 0;
        __syncthreads();
        part[t] = v + u;
        __syncthreads();
    }
    int run = (t > 0) ? part[t - 1] : 0;
    for (int i = 0; i < CH; ++i) {
        int idx = base + i;
        if (idx < NP) {
            g_rowp[idx]   = run;
            g_cursor[idx] = run;
            run += g_deg[idx];
        }
    }
    if (t == 0) g_rowp[NP] = N_EDGES;
}
__global__ void csr_fill_kernel(const int* __restrict__ src,
                                const int* __restrict__ dst) {
    int e = blockIdx.x * 256 + threadIdx.x;
    if (e < N_EDGES) {
        int p = atomicAdd(&g_cursor[dst[e]], 1);
        g_csr[p] = src[e];
    }
}

// ================= aggregation (tf32-rounded output) =================
__global__ __launch_bounds__(192) void gather_kernel() {
    int g = threadIdx.x / 48;
    int c = threadIdx.x % 48;
    int n = blockIdx.x * 4 + g;
    int beg = __ldg(&g_rowp[n]);
    int end = __ldg(&g_rowp[n + 1]);
    const float4* h4 = reinterpret_cast<const float4*>(g_h);
    float4 v = make_float4(0.f, 0.f, 0.f, 0.f);
    int i = beg;
    for (; i + 2 <= end; i += 2) {
        int s0 = __ldg(&g_csr[i]);
        int s1 = __ldg(&g_csr[i + 1]);
        float4 a = h4[(size_t)s0 * 48 + c];
        float4 b = h4[(size_t)s1 * 48 + c];
        v.x += a.x + b.x; v.y += a.y + b.y;
        v.z += a.z + b.z; v.w += a.w + b.w;
    }
    if (i < end) {
        int s0 = __ldg(&g_csr[i]);
        float4 a = h4[(size_t)s0 * 48 + c];
        v.x += a.x; v.y += a.y; v.z += a.z; v.w += a.w;
    }
    v.x = rtf32(v.x); v.y = rtf32(v.y); v.z = rtf32(v.z); v.w = rtf32(v.w);
    reinterpret_cast<float4*>(g_hs)[(size_t)n * 48 + c] = v;
}

// ================= GRU gate fusion (tf32-rounded h) =================
__global__ void gate_kernel() {
    int idx = blockIdx.x * blockDim.x + threadIdx.x;
    if (idx >= N_NODES * 48) return;
    int n = idx / 48;
    int f4 = idx - n * 48;
    const float4* gi = reinterpret_cast<const float4*>(g_gi) + (size_t)n * 144 + f4;
    const float4* gh = reinterpret_cast<const float4*>(g_gh) + (size_t)n * 144 + f4;
    float4 gir = gi[0],  ghr = gh[0];
    float4 giz = gi[48], ghz = gh[48];
    float4 gin = gi[96], ghn = gh[96];
    float4* hp = reinterpret_cast<float4*>(g_h) + (size_t)n * 48 + f4;
    float4 h = *hp, o;
    #define GATE1(X) { \
        float r = 1.f / (1.f + expf(-(gir.X + ghr.X))); \
        float z = 1.f / (1.f + expf(-(giz.X + ghz.X))); \
        float nn = tanhf(gin.X + r * ghn.X); \
        o.X = rtf32((1.f - z) * nn + z * h.X); }
    GATE1(x) GATE1(y) GATE1(z) GATE1(w)
    #undef GATE1
    *hp = o;
}

// ================= mma.sync tf32 GEMM, float2 fragment loads =================
// k-permutation trick: inside each m16n8k8 atom, atom column c maps to global
// k = 2*(c%4) + (c>=4). Applied to BOTH A and B fragments, the reduction is
// unchanged, and each thread's two k-slots (lc, lc+4) become ADJACENT global
// columns (2lc, 2lc+1) -> one float2 LDS from linear smem. Halves fragment LDS.
// SA=40: LDS.64 half-warp phases conflict-free ((4*lr+lc) mod 16 bijective).
// Warps 4x2; warp tile (MA*16) x 32; CTA tile (MA*64) x 64; BK=32, 2-stage cp.async.

#define SA 40

__device__ __forceinline__ void mma_tf32(float* c, const uint32_t* a, const uint32_t* b) {
    asm volatile(
        "mma.sync.aligned.m16n8k8.row.col.f32.tf32.tf32.f32 "
        "{%0,%1,%2,%3}, {%4,%5,%6,%7}, {%8,%9}, {%0,%1,%2,%3};"
        : "+f"(c[0]), "+f"(c[1]), "+f"(c[2]), "+f"(c[3])
        : "r"(a[0]), "r"(a[1]), "r"(a[2]), "r"(a[3]), "r"(b[0]), "r"(b[1]));
}
__device__ __forceinline__ void cp16(uint32_t saddr, const float* g, int pred) {
    int sz = pred ? 16 : 0;
    asm volatile("cp.async.cg.shared.global [%0], [%1], 16, %2;"
                 :: "r"(saddr), "l"(g), "r"(sz) : "memory");
}

template <int MA>
__global__ __launch_bounds__(256)
void gemm_mma_kernel(const float* __restrict__ A0, const float* __restrict__ A1,
                     const float* __restrict__ B0, const float* __restrict__ B1,
                     const float* __restrict__ bias0, const float* __restrict__ bias1,
                     float* __restrict__ C0, float* __restrict__ C1,
                     int Ntot, int Mstore, int ldc, int act) {
    constexpr int AROWS = MA * 64;
    constexpr int AST   = AROWS * SA;
    constexpr int BST   = 64 * SA;
    constexpr int STG   = AST + BST;

    extern __shared__ float sm[];
    uint32_t smb;
    asm("{ .reg .u64 t; cvta.to.shared.u64 t, %1; cvt.u32.u64 %0, t; }"
        : "=r"(smb) : "l"(sm));

    int z = blockIdx.z;
    const float* A    = z ? A1    : A0;
    const float* B    = z ? B1    : B0;
    const float* bias = z ? bias1 : bias0;
    float*       C    = z ? C1    : C0;

    int tid  = threadIdx.x;
    int lane = tid & 31, wid = tid >> 5;
    int wr = wid & 3, wc2 = wid >> 2;
    int lr = lane >> 2, lc = lane & 3;
    int m0 = blockIdx.y * AROWS;
    int n0 = blockIdx.x * 64;

    int a_row[2 * MA], a_c4[2 * MA], b_row[2], b_c4[2];
    #pragma unroll
    for (int i = 0; i < 2 * MA; ++i) { int it = i * 256 + tid; a_row[i] = it >> 3; a_c4[i] = it & 7; }
    #pragma unroll
    for (int i = 0; i < 2; ++i) { int it = i * 256 + tid; b_row[i] = it >> 3; b_c4[i] = it & 7; }

    #define PREFETCH(s, st) { \
        uint32_t sa_ = smb + (st) * (STG * 4); \
        _Pragma("unroll") \
        for (int i = 0; i < 2 * MA; ++i) \
            cp16(sa_ + (a_row[i] * SA + a_c4[i] * 4) * 4, \
                 A + (size_t)(m0 + a_row[i]) * FDIM + (s) * 32 + a_c4[i] * 4, 1); \
        uint32_t sb_ = sa_ + AST * 4; \
        _Pragma("unroll") \
        for (int i = 0; i < 2; ++i) \
            cp16(sb_ + (b_row[i] * SA + b_c4[i] * 4) * 4, \
                 B + (size_t)(n0 + b_row[i]) * FDIM + (s) * 32 + b_c4[i] * 4, \
                 (n0 + b_row[i]) < Ntot); \
        asm volatile("cp.async.commit_group;" ::: "memory"); \
    }

    float acc[MA][4][4];
    #pragma unroll
    for (int i = 0; i < MA; ++i)
        #pragma unroll
        for (int j = 0; j < 4; ++j)
            #pragma unroll
            for (int q = 0; q < 4; ++q) acc[i][j][q] = 0.f;

    PREFETCH(0, 0);

    #pragma unroll 1
    for (int s = 0; s < 6; ++s) {
        if (s + 1 < 6) {
            PREFETCH(s + 1, (s + 1) & 1);
            asm volatile("cp.async.wait_group 1;" ::: "memory");
        } else {
            asm volatile("cp.async.wait_group 0;" ::: "memory");
        }
        __syncthreads();

        const float* Asp = sm + (s & 1) * STG;
        const float* Bsp = Asp + AST;
        #pragma unroll
        for (int ks = 0; ks < 4; ++ks) {
            int co = ks * 8 + lc * 2;          // adjacent global k pair (2lc, 2lc+1)
            uint32_t a[MA][4], b[4][2];
            #pragma unroll
            for (int ma = 0; ma < MA; ++ma) {
                int r = wr * (MA * 16) + ma * 16 + lr;
                float2 lo = *reinterpret_cast<const float2*>(Asp + r * SA + co);
                float2 hi = *reinterpret_cast<const float2*>(Asp + (r + 8) * SA + co);
                a[ma][0] = __float_as_uint(lo.x);   // atom col lc
                a[ma][1] = __float_as_uint(hi.x);
                a[ma][2] = __float_as_uint(lo.y);   // atom col lc+4
                a[ma][3] = __float_as_uint(hi.y);
            }
            #pragma unroll
            for (int na = 0; na < 4; ++na) {
                int bn = wc2 * 32 + na * 8 + lr;
                float2 bb = *reinterpret_cast<const float2*>(Bsp + bn * SA + co);
                b[na][0] = __float_as_uint(bb.x);   // atom col lc
                b[na][1] = __float_as_uint(bb.y);   // atom col lc+4
            }
            #pragma unroll
            for (int ma = 0; ma < MA; ++ma)
                #pragma unroll
                for (int na = 0; na < 4; ++na)
                    mma_tf32(acc[ma][na], a[ma], b[na]);
        }
        __syncthreads();
    }

    // ---- epilogue ----
    #pragma unroll
    for (int ma = 0; ma < MA; ++ma) {
        #pragma unroll
        for (int na = 0; na < 4; ++na) {
            int row = m0 + wr * (MA * 16) + ma * 16 + lr;
            int col = n0 + wc2 * 32 + na * 8 + lc * 2;
            #pragma unroll
            for (int half = 0; half < 2; ++half) {
                int r = row + half * 8;
                if (r >= Mstore) continue;
                float v0 = acc[ma][na][half * 2 + 0];
                float v1 = acc[ma][na][half * 2 + 1];
                if (col + 1 < Ntot) {
                    v0 += __ldg(bias + col);
                    v1 += __ldg(bias + col + 1);
                    if (act) { v0 = 1.f / (1.f + expf(-v0)); v1 = 1.f / (1.f + expf(-v1)); }
                    *reinterpret_cast<float2*>(C + (size_t)r * ldc + col) = make_float2(v0, v1);
                } else if (col < Ntot) {
                    v0 += __ldg(bias + col);
                    if (act) v0 = 1.f / (1.f + expf(-v0));
                    C[(size_t)r * ldc + col] = v0;
                }
            }
        }
    }
    #undef PREFETCH
}

// ================= launch =================
extern "C" void kernel_launch(void* const* d_in, const int* in_sizes, int n_in,
                              void* d_out, int out_size) {
    const int*   prop_ids = (const int*)d_in[0];
    const int*   src      = (const int*)d_in[1];
    const int*   dst      = (const int*)d_in[2];
    const float* embed    = (const float*)d_in[3];
    const float* W_edge   = (const float*)d_in[4];
    const float* W_ih     = (const float*)d_in[5];
    const float* W_hh     = (const float*)d_in[6];
    const float* b_ih     = (const float*)d_in[7];
    const float* b_hh     = (const float*)d_in[8];
    const float* conv_w   = (const float*)d_in[9];
    const float* conv_b   = (const float*)d_in[10];
    float* out = (float*)d_out;

    float *h, *hs, *gi, *gh, *wc, *whr, *cwr;
    cudaGetSymbolAddress((void**)&h,   g_h);
    cudaGetSymbolAddress((void**)&hs,  g_hs);
    cudaGetSymbolAddress((void**)&gi,  g_gi);
    cudaGetSymbolAddress((void**)&gh,  g_gh);
    cudaGetSymbolAddress((void**)&wc,  g_wc);
    cudaGetSymbolAddress((void**)&whr, g_whr);
    cudaGetSymbolAddress((void**)&cwr, g_cwr);

    const int SMEM2 = 2 * (128 * SA + 64 * SA) * 4;   // MA=2: 61440 B
    const int SMEM4 = 2 * (256 * SA + 64 * SA) * 4;   // MA=4: 102400 B

    static int smem_set = 0;
    if (!smem_set) {
        cudaFuncSetAttribute(gemm_mma_kernel<2>,
                             cudaFuncAttributeMaxDynamicSharedMemorySize, SMEM2);
        cudaFuncSetAttribute(gemm_mma_kernel<4>,
                             cudaFuncAttributeMaxDynamicSharedMemorySize, SMEM4);
        smem_set = 1;
    }

    const int MT4 = NP / 256;                       // 196
    const int MT2 = NP / 128;                       // 392
    const dim3 grid_one(F3 / 64, MT4, 1);           // single 576-GEMM, 256-row tiles
    const dim3 grid_two(F3 / 64, MT4, 2);           // gi + gh fused
    const dim3 grid_cls((NCLS2 + 63) / 64, MT2, 1); // class GEMM, 128-row tiles
    const int gate_grid = (N_NODES * 48 + 255) / 256;

    // ---- setup (big GEMM is launch #4 so ncu captures it) ----
    embed_gather_kernel<<<N_NODES, FDIM>>>(prop_ids, embed);                    // 1
    fold_kernel<<<F3, FDIM>>>(W_ih, W_edge);                                    // 2
    round_w_kernel<<<F3 + NCLS2, FDIM>>>(W_hh, conv_w);                         // 3
    gemm_mma_kernel<4><<<grid_one, 256, SMEM4>>>(h, h, whr, whr, b_hh, b_hh,
                                                 gh, gh, F3, NP, F3, 0);        // 4: step-1 gh
    zero_deg_kernel<<<(NP + 255) / 256, 256>>>();                               // 5
    csr_count_kernel<<<(N_EDGES + 255) / 256, 256>>>(dst);                      // 6
    scan_kernel<<<1, 1024>>>();                                                 // 7
    csr_fill_kernel<<<(N_EDGES + 255) / 256, 256>>>(src, dst);                  // 8

    // ---- step 1 (gh already computed) ----
    gather_kernel<<<NP / 4, 192>>>();
    gemm_mma_kernel<4><<<grid_one, 256, SMEM4>>>(hs, hs, wc, wc, b_ih, b_ih,
                                                 gi, gi, F3, NP, F3, 0);
    gate_kernel<<<gate_grid, 256>>>();

    // ---- steps 2..6 ----
    for (int step = 2; step <= STEP_MAX; ++step) {
        gather_kernel<<<NP / 4, 192>>>();
        gemm_mma_kernel<4><<<grid_two, 256, SMEM4>>>(hs, h, wc, whr, b_ih, b_hh,
                                                     gi, gh, F3, NP, F3, 0);
        gate_kernel<<<gate_grid, 256>>>();
        int s = step - STEP_MIN;
        gemm_mma_kernel<2><<<grid_cls, 256, SMEM2>>>(h, h, cwr, cwr, conv_b, conv_b,
                                                     out + s * NCLS2, out + s * NCLS2,
                                                     NCLS2, N_NODES, 5 * NCLS2, 1);
    }
}

// round 10
// speedup vs baseline: 1.5305x; 1.1804x over previous
#include <cuda_runtime.h>
#include <math.h>
#include <stdint.h>

#define N_NODES 50000
#define NP      50176              // 392*128, 1024*49
#define N_EDGES 800000
#define EMBED_DIM 64
#define N_PROPS 3
#define FDIM 192
#define F3 576
#define NCLS2 100
#define STEP_MIN 2
#define STEP_MAX 6

// ---------------- device scratch ----------------
__device__ float g_h0 [(size_t)NP * FDIM];
__device__ float g_h1 [(size_t)NP * FDIM];
__device__ float g_hs [(size_t)NP * FDIM];
__device__ float g_wc [(size_t)F3 * FDIM];
__device__ float g_whr[(size_t)F3 * FDIM];
__device__ float g_cwr[(size_t)NCLS2 * FDIM];
__device__ int   g_deg[NP];
__device__ int   g_rowp[NP + 1];
__device__ int   g_cursor[NP];
__device__ int   g_csr[N_EDGES];

// RN-round fp32 -> tf32-representable fp32
__device__ __forceinline__ float rtf32(float x) {
    uint32_t u = __float_as_uint(x);
    u = (u + 0xfffu + ((u >> 13) & 1u)) & 0xFFFFE000u;
    return __uint_as_float(u);
}

// ================= embedding gather + deg zero =================
__global__ void embed_gather_kernel(const int* __restrict__ prop_ids,
                                    const float* __restrict__ table) {
    int n = blockIdx.x;
    int f = threadIdx.x;
    float v = 0.f;
    if (n < N_NODES) {
        int p = f >> 6;
        int e = f & 63;
        int id = prop_ids[n * N_PROPS + p];
        v = rtf32(table[(size_t)id * EMBED_DIM + e]);
    }
    g_h0[(size_t)n * FDIM + f] = v;
    if (f == 0) g_deg[n] = 0;
}

// ================= fold + round weights (merged) =================
// blocks [0,F3): wc = round(W_ih @ W_edge); [F3,2F3): whr; [2F3,2F3+NCLS2): cwr
__global__ void foldround_kernel(const float* __restrict__ W_ih,
                                 const float* __restrict__ W_edge,
                                 const float* __restrict__ W_hh,
                                 const float* __restrict__ conv_w) {
    int i = blockIdx.x;
    int j = threadIdx.x;
    if (i < F3) {
        float s = 0.f;
        #pragma unroll 8
        for (int k = 0; k < FDIM; ++k)
            s = fmaf(__ldg(W_ih + i * FDIM + k), __ldg(W_edge + k * FDIM + j), s);
        g_wc[(size_t)i * FDIM + j] = rtf32(s);
    } else if (i < 2 * F3) {
        int r = i - F3;
        g_whr[(size_t)r * FDIM + j] = rtf32(__ldg(W_hh + (size_t)r * FDIM + j));
    } else {
        int r = i - 2 * F3;
        g_cwr[(size_t)r * FDIM + j] = rtf32(__ldg(conv_w + (size_t)r * FDIM + j));
    }
}

// ================= CSR build =================
__global__ void csr_count_kernel(const int* __restrict__ dst) {
    int e = blockIdx.x * 256 + threadIdx.x;
    if (e < N_EDGES) atomicAdd(&g_deg[dst[e]], 1);
}
__global__ __launch_bounds__(1024) void scan_kernel() {
    __shared__ int part[1024];
    const int CH = 49;                 // 1024*49 = 50176 = NP
    int t = threadIdx.x;
    int base = t * CH;
    int s = 0;
    #pragma unroll 7
    for (int i = 0; i < CH; ++i) {
        int idx = base + i;
        if (idx < NP) s += g_deg[idx];
    }
    part[t] = s;
    __syncthreads();
    for (int off = 1; off < 1024; off <<= 1) {
        int v = part[t];
        int u = (t >= off) ? part[t - off] : 0;
        __syncthreads();
        part[t] = v + u;
        __syncthreads();
    }
    int run = (t > 0) ? part[t - 1] : 0;
    for (int i = 0; i < CH; ++i) {
        int idx = base + i;
        if (idx < NP) {
            g_rowp[idx]   = run;
            g_cursor[idx] = run;
            run += g_deg[idx];
        }
    }
    if (t == 0) g_rowp[NP] = N_EDGES;
}
__global__ void csr_fill_kernel(const int* __restrict__ src,
                                const int* __restrict__ dst) {
    int e = blockIdx.x * 256 + threadIdx.x;
    if (e < N_EDGES) {
        int p = atomicAdd(&g_cursor[dst[e]], 1);
        g_csr[p] = src[e];
    }
}

// ================= aggregation: hs[n] = sum h[src] (tf32-rounded) =================
__global__ __launch_bounds__(192) void gather_kernel(const float* __restrict__ hcur) {
    int g = threadIdx.x / 48;
    int c = threadIdx.x % 48;
    int n = blockIdx.x * 4 + g;
    int beg = __ldg(&g_rowp[n]);
    int end = __ldg(&g_rowp[n + 1]);
    const float4* h4 = reinterpret_cast<const float4*>(hcur);
    float4 v = make_float4(0.f, 0.f, 0.f, 0.f);
    int i = beg;
    for (; i + 2 <= end; i += 2) {
        int s0 = __ldg(&g_csr[i]);
        int s1 = __ldg(&g_csr[i + 1]);
        float4 a = h4[(size_t)s0 * 48 + c];
        float4 b = h4[(size_t)s1 * 48 + c];
        v.x += a.x + b.x; v.y += a.y + b.y;
        v.z += a.z + b.z; v.w += a.w + b.w;
    }
    if (i < end) {
        int s0 = __ldg(&g_csr[i]);
        float4 a = h4[(size_t)s0 * 48 + c];
        v.x += a.x; v.y += a.y; v.z += a.z; v.w += a.w;
    }
    v.x = rtf32(v.x); v.y = rtf32(v.y); v.z = rtf32(v.z); v.w = rtf32(v.w);
    reinterpret_cast<float4*>(g_hs)[(size_t)n * 48 + c] = v;
}

// ================= shared mma helpers =================
#define SA 40

__device__ __forceinline__ void mma_tf32(float* c, const uint32_t* a, const uint32_t* b) {
    asm volatile(
        "mma.sync.aligned.m16n8k8.row.col.f32.tf32.tf32.f32 "
        "{%0,%1,%2,%3}, {%4,%5,%6,%7}, {%8,%9}, {%0,%1,%2,%3};"
        : "+f"(c[0]), "+f"(c[1]), "+f"(c[2]), "+f"(c[3])
        : "r"(a[0]), "r"(a[1]), "r"(a[2]), "r"(a[3]), "r"(b[0]), "r"(b[1]));
}
__device__ __forceinline__ void cp16(uint32_t saddr, const float* g, int pred) {
    int sz = pred ? 16 : 0;
    asm volatile("cp.async.cg.shared.global [%0], [%1], 16, %2;"
                 :: "r"(saddr), "l"(g), "r"(sz) : "memory");
}
__device__ __forceinline__ float sigm(float x) { return 1.f / (1.f + expf(-x)); }

// ================= FUSED GRU step kernel =================
// Per CTA: 128 nodes x 32 feature-cols of h_new.
// Accumulators: s_r = hs@wc_r + h@whr_r (K=384 concat), s_z likewise,
//               gin = hs@wc_n, ghn = h@whr_n.
// 12 K-slabs of 32: slabs 0-5 A=hs,B=wc; slabs 6-11 A=h,B=whr.
// B tile = 3 chunks (r,z,n) x 32 rows. One A fragment feeds 3 HMMA chains.
// Epilogue: gate math + write h_new (tf32-rounded). k-permuted float2 LDS.

#define FAST (128 * SA)
#define FBST (96 * SA)
#define FSTG (FAST + FBST)
#define FSMEM (2 * FSTG * 4)

__global__ __launch_bounds__(256)
void gru_fused_kernel(const float* __restrict__ hs, const float* __restrict__ hold,
                      const float* __restrict__ wc, const float* __restrict__ whr,
                      const float* __restrict__ b_ih, const float* __restrict__ b_hh,
                      float* __restrict__ hnew) {
    extern __shared__ float sm[];
    uint32_t smb;
    asm("{ .reg .u64 t; cvta.to.shared.u64 t, %1; cvt.u32.u64 %0, t; }"
        : "=r"(smb) : "l"(sm));

    int tid  = threadIdx.x;
    int lane = tid & 31, wid = tid >> 5;
    int wr = wid & 3, wf = wid >> 2;           // 4 m-warps x 2 f-warps
    int lr = lane >> 2, lc = lane & 3;
    int m0 = blockIdx.y * 128;
    int f0 = blockIdx.x * 32;                  // feature-col tile [f0, f0+32)

    int a_row[4], a_c4[4], b_row[3], b_c4[3];
    #pragma unroll
    for (int i = 0; i < 4; ++i) { int it = i * 256 + tid; a_row[i] = it >> 3; a_c4[i] = it & 7; }
    #pragma unroll
    for (int i = 0; i < 3; ++i) { int it = i * 256 + tid; b_row[i] = it >> 3; b_c4[i] = it & 7; }

    #define FPREF(s, st) { \
        const float* Ap = (s) < 6 ? hs : hold; \
        const float* Bp = (s) < 6 ? wc : whr; \
        int ko = ((s) < 6 ? (s) : (s) - 6) * 32; \
        uint32_t sa_ = smb + (st) * (FSTG * 4); \
        _Pragma("unroll") \
        for (int i = 0; i < 4; ++i) \
            cp16(sa_ + (a_row[i] * SA + a_c4[i] * 4) * 4, \
                 Ap + (size_t)(m0 + a_row[i]) * FDIM + ko + a_c4[i] * 4, 1); \
        uint32_t sb_ = sa_ + FAST * 4; \
        _Pragma("unroll") \
        for (int i = 0; i < 3; ++i) { \
            int q_ = b_row[i] >> 5; \
            int grow_ = q_ * FDIM + f0 + (b_row[i] & 31); \
            cp16(sb_ + (b_row[i] * SA + b_c4[i] * 4) * 4, \
                 Bp + (size_t)grow_ * FDIM + ko + b_c4[i] * 4, 1); \
        } \
        asm volatile("cp.async.commit_group;" ::: "memory"); \
    }

    float ar[2][2][4], az[2][2][4], ai[2][2][4], ah[2][2][4];
    #pragma unroll
    for (int i = 0; i < 2; ++i)
        #pragma unroll
        for (int j = 0; j < 2; ++j)
            #pragma unroll
            for (int q = 0; q < 4; ++q) {
                ar[i][j][q] = 0.f; az[i][j][q] = 0.f;
                ai[i][j][q] = 0.f; ah[i][j][q] = 0.f;
            }

    FPREF(0, 0);

    #pragma unroll 1
    for (int s = 0; s < 12; ++s) {
        if (s + 1 < 12) {
            FPREF(s + 1, (s + 1) & 1);
            asm volatile("cp.async.wait_group 1;" ::: "memory");
        } else {
            asm volatile("cp.async.wait_group 0;" ::: "memory");
        }
        __syncthreads();

        const float* Asp = sm + (s & 1) * FSTG;
        const float* Bsp = Asp + FAST;
        bool first = (s < 6);

        #pragma unroll
        for (int ks = 0; ks < 4; ++ks) {
            int co = ks * 8 + lc * 2;
            uint32_t a[2][4], b[3][2][2];
            #pragma unroll
            for (int ma = 0; ma < 2; ++ma) {
                int r = wr * 32 + ma * 16 + lr;
                float2 lo = *reinterpret_cast<const float2*>(Asp + r * SA + co);
                float2 hi = *reinterpret_cast<const float2*>(Asp + (r + 8) * SA + co);
                a[ma][0] = __float_as_uint(lo.x);
                a[ma][1] = __float_as_uint(hi.x);
                a[ma][2] = __float_as_uint(lo.y);
                a[ma][3] = __float_as_uint(hi.y);
            }
            #pragma unroll
            for (int q = 0; q < 3; ++q)
                #pragma unroll
                for (int na = 0; na < 2; ++na) {
                    int bn = q * 32 + wf * 16 + na * 8 + lr;
                    float2 bb = *reinterpret_cast<const float2*>(Bsp + bn * SA + co);
                    b[q][na][0] = __float_as_uint(bb.x);
                    b[q][na][1] = __float_as_uint(bb.y);
                }
            #pragma unroll
            for (int ma = 0; ma < 2; ++ma)
                #pragma unroll
                for (int na = 0; na < 2; ++na) {
                    mma_tf32(ar[ma][na], a[ma], b[0][na]);
                    mma_tf32(az[ma][na], a[ma], b[1][na]);
                }
            if (first) {
                #pragma unroll
                for (int ma = 0; ma < 2; ++ma)
                    #pragma unroll
                    for (int na = 0; na < 2; ++na)
                        mma_tf32(ai[ma][na], a[ma], b[2][na]);
            } else {
                #pragma unroll
                for (int ma = 0; ma < 2; ++ma)
                    #pragma unroll
                    for (int na = 0; na < 2; ++na)
                        mma_tf32(ah[ma][na], a[ma], b[2][na]);
            }
        }
        __syncthreads();
    }

    // ---- gate epilogue ----
    #pragma unroll
    for (int ma = 0; ma < 2; ++ma) {
        #pragma unroll
        for (int half = 0; half < 2; ++half) {
            int rr = m0 + wr * 32 + ma * 16 + half * 8 + lr;
            if (rr >= N_NODES) continue;
            #pragma unroll
            for (int na = 0; na < 2; ++na) {
                int c0 = f0 + wf * 16 + na * 8 + lc * 2;
                float2 ho = *reinterpret_cast<const float2*>(hold + (size_t)rr * FDIM + c0);
                float2 o;
                #pragma unroll
                for (int e = 0; e < 2; ++e) {
                    int c = c0 + e;
                    int q = half * 2 + e;
                    float sr = ar[ma][na][q] + __ldg(b_ih + c) + __ldg(b_hh + c);
                    float sz = az[ma][na][q] + __ldg(b_ih + FDIM + c) + __ldg(b_hh + FDIM + c);
                    float gn = ai[ma][na][q] + __ldg(b_ih + 2 * FDIM + c);
                    float hn = ah[ma][na][q] + __ldg(b_hh + 2 * FDIM + c);
                    float r_ = sigm(sr);
                    float z_ = sigm(sz);
                    float nn = tanhf(gn + r_ * hn);
                    float hv = e ? ho.y : ho.x;
                    float res = rtf32((1.f - z_) * nn + z_ * hv);
                    if (e) o.y = res; else o.x = res;
                }
                *reinterpret_cast<float2*>(hnew + (size_t)rr * FDIM + c0) = o;
            }
        }
    }
    #undef FPREF
}

// ================= class-logits GEMM (MA=2, as in R9) =================
#define CAST (128 * SA)
#define CBST (64 * SA)
#define CSTG (CAST + CBST)
#define CSMEM (2 * CSTG * 4)

__global__ __launch_bounds__(256)
void cls_gemm_kernel(const float* __restrict__ A, const float* __restrict__ B,
                     const float* __restrict__ bias, float* __restrict__ C,
                     int Ntot, int Mstore, int ldc) {
    extern __shared__ float sm[];
    uint32_t smb;
    asm("{ .reg .u64 t; cvta.to.shared.u64 t, %1; cvt.u32.u64 %0, t; }"
        : "=r"(smb) : "l"(sm));

    int tid  = threadIdx.x;
    int lane = tid & 31, wid = tid >> 5;
    int wr = wid & 3, wc2 = wid >> 2;
    int lr = lane >> 2, lc = lane & 3;
    int m0 = blockIdx.y * 128;
    int n0 = blockIdx.x * 64;

    int a_row[4], a_c4[4], b_row[2], b_c4[2];
    #pragma unroll
    for (int i = 0; i < 4; ++i) { int it = i * 256 + tid; a_row[i] = it >> 3; a_c4[i] = it & 7; }
    #pragma unroll
    for (int i = 0; i < 2; ++i) { int it = i * 256 + tid; b_row[i] = it >> 3; b_c4[i] = it & 7; }

    #define CPREF(s, st) { \
        uint32_t sa_ = smb + (st) * (CSTG * 4); \
        _Pragma("unroll") \
        for (int i = 0; i < 4; ++i) \
            cp16(sa_ + (a_row[i] * SA + a_c4[i] * 4) * 4, \
                 A + (size_t)(m0 + a_row[i]) * FDIM + (s) * 32 + a_c4[i] * 4, 1); \
        uint32_t sb_ = sa_ + CAST * 4; \
        _Pragma("unroll") \
        for (int i = 0; i < 2; ++i) \
            cp16(sb_ + (b_row[i] * SA + b_c4[i] * 4) * 4, \
                 B + (size_t)(n0 + b_row[i]) * FDIM + (s) * 32 + b_c4[i] * 4, \
                 (n0 + b_row[i]) < Ntot); \
        asm volatile("cp.async.commit_group;" ::: "memory"); \
    }

    float acc[2][4][4];
    #pragma unroll
    for (int i = 0; i < 2; ++i)
        #pragma unroll
        for (int j = 0; j < 4; ++j)
            #pragma unroll
            for (int q = 0; q < 4; ++q) acc[i][j][q] = 0.f;

    CPREF(0, 0);

    #pragma unroll 1
    for (int s = 0; s < 6; ++s) {
        if (s + 1 < 6) {
            CPREF(s + 1, (s + 1) & 1);
            asm volatile("cp.async.wait_group 1;" ::: "memory");
        } else {
            asm volatile("cp.async.wait_group 0;" ::: "memory");
        }
        __syncthreads();

        const float* Asp = sm + (s & 1) * CSTG;
        const float* Bsp = Asp + CAST;
        #pragma unroll
        for (int ks = 0; ks < 4; ++ks) {
            int co = ks * 8 + lc * 2;
            uint32_t a[2][4], b[4][2];
            #pragma unroll
            for (int ma = 0; ma < 2; ++ma) {
                int r = wr * 32 + ma * 16 + lr;
                float2 lo = *reinterpret_cast<const float2*>(Asp + r * SA + co);
                float2 hi = *reinterpret_cast<const float2*>(Asp + (r + 8) * SA + co);
                a[ma][0] = __float_as_uint(lo.x);
                a[ma][1] = __float_as_uint(hi.x);
                a[ma][2] = __float_as_uint(lo.y);
                a[ma][3] = __float_as_uint(hi.y);
            }
            #pragma unroll
            for (int na = 0; na < 4; ++na) {
                int bn = wc2 * 32 + na * 8 + lr;
                float2 bb = *reinterpret_cast<const float2*>(Bsp + bn * SA + co);
                b[na][0] = __float_as_uint(bb.x);
                b[na][1] = __float_as_uint(bb.y);
            }
            #pragma unroll
            for (int ma = 0; ma < 2; ++ma)
                #pragma unroll
                for (int na = 0; na < 4; ++na)
                    mma_tf32(acc[ma][na], a[ma], b[na]);
        }
        __syncthreads();
    }

    #pragma unroll
    for (int ma = 0; ma < 2; ++ma) {
        #pragma unroll
        for (int na = 0; na < 4; ++na) {
            int row = m0 + wr * 32 + ma * 16 + lr;
            int col = n0 + wc2 * 32 + na * 8 + lc * 2;
            #pragma unroll
            for (int half = 0; half < 2; ++half) {
                int r = row + half * 8;
                if (r >= Mstore) continue;
                float v0 = acc[ma][na][half * 2 + 0];
                float v1 = acc[ma][na][half * 2 + 1];
                if (col + 1 < Ntot) {
                    v0 = sigm(v0 + __ldg(bias + col));
                    v1 = sigm(v1 + __ldg(bias + col + 1));
                    *reinterpret_cast<float2*>(C + (size_t)r * ldc + col) = make_float2(v0, v1);
                } else if (col < Ntot) {
                    v0 = sigm(v0 + __ldg(bias + col));
                    C[(size_t)r * ldc + col] = v0;
                }
            }
        }
    }
    #undef CPREF
}

// ================= launch =================
extern "C" void kernel_launch(void* const* d_in, const int* in_sizes, int n_in,
                              void* d_out, int out_size) {
    const int*   prop_ids = (const int*)d_in[0];
    const int*   src      = (const int*)d_in[1];
    const int*   dst      = (const int*)d_in[2];
    const float* embed    = (const float*)d_in[3];
    const float* W_edge   = (const float*)d_in[4];
    const float* W_ih     = (const float*)d_in[5];
    const float* W_hh     = (const float*)d_in[6];
    const float* b_ih     = (const float*)d_in[7];
    const float* b_hh     = (const float*)d_in[8];
    const float* conv_w   = (const float*)d_in[9];
    const float* conv_b   = (const float*)d_in[10];
    float* out = (float*)d_out;

    float *h0, *h1, *hs, *wc, *whr, *cwr;
    cudaGetSymbolAddress((void**)&h0,  g_h0);
    cudaGetSymbolAddress((void**)&h1,  g_h1);
    cudaGetSymbolAddress((void**)&hs,  g_hs);
    cudaGetSymbolAddress((void**)&wc,  g_wc);
    cudaGetSymbolAddress((void**)&whr, g_whr);
    cudaGetSymbolAddress((void**)&cwr, g_cwr);

    static int smem_set = 0;
    if (!smem_set) {
        cudaFuncSetAttribute(gru_fused_kernel,
                             cudaFuncAttributeMaxDynamicSharedMemorySize, FSMEM);
        cudaFuncSetAttribute(cls_gemm_kernel,
                             cudaFuncAttributeMaxDynamicSharedMemorySize, CSMEM);
        smem_set = 1;
    }

    const int MT = NP / 128;                       // 392
    const dim3 grid_gru(FDIM / 32, MT, 1);         // 6 x 392
    const dim3 grid_cls((NCLS2 + 63) / 64, MT, 1); // 2 x 392

    // ---- setup ----
    embed_gather_kernel<<<NP, FDIM>>>(prop_ids, embed);                         // also zeroes deg
    csr_count_kernel<<<(N_EDGES + 255) / 256, 256>>>(dst);
    scan_kernel<<<1, 1024>>>();
    csr_fill_kernel<<<(N_EDGES + 255) / 256, 256>>>(src, dst);
    foldround_kernel<<<2 * F3 + NCLS2, FDIM>>>(W_ih, W_edge, W_hh, conv_w);

    // ---- steps ----
    float* bufs[2] = {h0, h1};
    for (int step = 1; step <= STEP_MAX; ++step) {
        float* hc = bufs[(step - 1) & 1];
        float* hn = bufs[step & 1];
        gather_kernel<<<NP / 4, 192>>>(hc);
        gru_fused_kernel<<<grid_gru, 256, FSMEM>>>(hs, hc, wc, whr, b_ih, b_hh, hn);
        if (step >= STEP_MIN) {
            int s = step - STEP_MIN;
            cls_gemm_kernel<<<grid_cls, 256, CSMEM>>>(hn, cwr, conv_b, out + s * NCLS2,
                                                      NCLS2, N_NODES, 5 * NCLS2);
        }
    }
}